// round 1
// baseline (speedup 1.0000x reference)
#include <cuda_runtime.h>
#include <math.h>

#define BB 16
#define NN 256
#define DD 128
#define KP 128   // pooled nodes = N * 0.5

// -------- scratch (device globals; no allocation allowed) --------
__device__ float d_logits[(size_t)BB * NN * NN];   // 4 MB, reused in-place by softmax
__device__ float d_h[(size_t)BB * NN * DD];        // 2 MB
__device__ float d_scores[BB * NN];

__device__ __forceinline__ float tanh_approx(float x) {
    float y;
    asm("tanh.approx.f32 %0, %1;" : "=f"(y) : "f"(x));
    return y;
}

// ============================================================================
// Kernel 1: logits[b,i,j] = sum_c v[c] * tanh( sum_d x_i[d] x_j[d] W[d,c] + bias[c] )
// Block = (i, b). Build A = x_i (*) W in smem, then register-tiled GEMM over
// j-tiles of 32. Symmetry: only j >= i computed; result written to (i,j) and (j,i).
// ============================================================================
#define APAD 132
#define XPAD 132
#define SMEM1 ((128 * APAD + 32 * XPAD + 128) * 4)

__global__ void __launch_bounds__(256, 2)
k1_logits(const float* __restrict__ x, const float* __restrict__ W,
          const float* __restrict__ bias, const float* __restrict__ v) {
    extern __shared__ float sm[];
    float* A  = sm;                   // [128][APAD]
    float* XJ = A + 128 * APAD;       // [32][XPAD]
    float* XI = XJ + 32 * XPAD;       // [128]

    const int b = blockIdx.y, i = blockIdx.x;
    const int tid = threadIdx.x;
    const int tc = tid & 15;          // c-group index (8 c's each)
    const int tj = tid >> 4;          // j index within tile (and tj+16)
    const float* xb = x + (size_t)b * NN * DD;

    if (tid < 128) XI[tid] = xb[(size_t)i * DD + tid];
    __syncthreads();

    // Build A[d][c] = x_i[d] * W[d][c]
    {
        int d  = tid >> 1;
        int c0 = (tid & 1) * 64;
        float xd = XI[d];
        const float4* wr = (const float4*)(W + (size_t)d * DD + c0);
        float4* ar = (float4*)(A + d * APAD + c0);
        #pragma unroll
        for (int k = 0; k < 16; k++) {
            float4 w4 = wr[k];
            ar[k] = make_float4(xd * w4.x, xd * w4.y, xd * w4.z, xd * w4.w);
        }
    }

    float br[8], vr[8];
    #pragma unroll
    for (int k = 0; k < 8; k++) { br[k] = bias[tc * 8 + k]; vr[k] = v[tc * 8 + k]; }

    float* Lrow = d_logits + ((size_t)b * NN + i) * NN;

    for (int jb = i; jb < NN; jb += 32) {
        __syncthreads();
        // cooperative load of 32 rows x[b, jb..jb+31, :]
        #pragma unroll
        for (int k = 0; k < 4; k++) {
            int r  = tid >> 3;
            int c4 = (tid & 7) + k * 8;
            int j  = jb + r;
            float4 val = (j < NN) ? ((const float4*)(xb + (size_t)j * DD))[c4]
                                  : make_float4(0.f, 0.f, 0.f, 0.f);
            ((float4*)(XJ + r * XPAD))[c4] = val;
        }
        __syncthreads();

        float q0[8], q1[8];
        #pragma unroll
        for (int k = 0; k < 8; k++) { q0[k] = 0.f; q1[k] = 0.f; }

        const float* xr0 = XJ + tj * XPAD;
        const float* xr1 = XJ + (tj + 16) * XPAD;
        const float* arow = A + tc * 8;

        #pragma unroll 4
        for (int d = 0; d < DD; d++) {
            float x0 = xr0[d];
            float x1 = xr1[d];
            const float4* ar = (const float4*)(arow + d * APAD);
            float4 a0 = ar[0], a1 = ar[1];
            q0[0] += a0.x * x0; q0[1] += a0.y * x0; q0[2] += a0.z * x0; q0[3] += a0.w * x0;
            q0[4] += a1.x * x0; q0[5] += a1.y * x0; q0[6] += a1.z * x0; q0[7] += a1.w * x0;
            q1[0] += a0.x * x1; q1[1] += a0.y * x1; q1[2] += a0.z * x1; q1[3] += a0.w * x1;
            q1[4] += a1.x * x1; q1[5] += a1.y * x1; q1[6] += a1.z * x1; q1[7] += a1.w * x1;
        }

        float s0 = 0.f, s1 = 0.f;
        #pragma unroll
        for (int k = 0; k < 8; k++) {
            s0 += vr[k] * tanh_approx(q0[k] + br[k]);
            s1 += vr[k] * tanh_approx(q1[k] + br[k]);
        }
        // reduce across the 16 c-groups (lanes 0..15 / 16..31 of each warp)
        #pragma unroll
        for (int o = 8; o >= 1; o >>= 1) {
            s0 += __shfl_xor_sync(0xffffffffu, s0, o);
            s1 += __shfl_xor_sync(0xffffffffu, s1, o);
        }
        if (tc == 0) {
            int j0 = jb + tj;
            int j1 = jb + tj + 16;
            if (j0 < NN) {
                Lrow[j0] = s0;
                d_logits[((size_t)b * NN + j0) * NN + i] = s0;
            }
            if (j1 < NN) {
                Lrow[j1] = s1;
                d_logits[((size_t)b * NN + j1) * NN + i] = s1;
            }
        }
    }
}

// ============================================================================
// Kernel 2: row softmax of d_logits in place.
// (logits symmetric => softmax over axis=1 == row softmax of row j gives R[j,i]
//  with att[b,i,j] = R[b,j,i].)
// ============================================================================
__global__ void __launch_bounds__(256)
k2_softmax() {
    const int b = blockIdx.y, r = blockIdx.x;
    float* row = d_logits + ((size_t)b * NN + r) * NN;
    const int tid = threadIdx.x;
    __shared__ float sred[8];
    __shared__ float sbc;

    float val = row[tid];
    float m = val;
    #pragma unroll
    for (int o = 16; o > 0; o >>= 1) m = fmaxf(m, __shfl_xor_sync(0xffffffffu, m, o));
    if ((tid & 31) == 0) sred[tid >> 5] = m;
    __syncthreads();
    float M = sred[0];
    #pragma unroll
    for (int w = 1; w < 8; w++) M = fmaxf(M, sred[w]);
    __syncthreads();

    float e = expf(val - M);
    float s = e;
    #pragma unroll
    for (int o = 16; o > 0; o >>= 1) s += __shfl_xor_sync(0xffffffffu, s, o);
    if ((tid & 31) == 0) sred[tid >> 5] = s;
    __syncthreads();
    if (tid == 0) {
        float S = 0.f;
        #pragma unroll
        for (int w = 0; w < 8; w++) S += sred[w];
        sbc = 1.f / S;
    }
    __syncthreads();
    row[tid] = e * sbc;
}

// ============================================================================
// Kernel 3: agg = R^T @ x ; h = agg@pwa_w + x@pwoa_w + biases; BN; selu;
// scores = sigmoid(h @ pool_w + pool_b). Block = (i-tile of 32, b).
// ============================================================================
#define SMEM3 ((32 * 36 + 3 * 32 * 132) * 4)

__global__ void __launch_bounds__(256)
k3_agg_h(const float* __restrict__ x,
         const float* __restrict__ pwa_w, const float* __restrict__ pwa_b,
         const float* __restrict__ pwoa_w, const float* __restrict__ pwoa_b,
         const float* __restrict__ bn_g, const float* __restrict__ bn_b,
         const float* __restrict__ bn_m, const float* __restrict__ bn_v,
         const float* __restrict__ pool_w, const float* __restrict__ pool_b) {
    extern __shared__ float sm3[];
    float* Rs  = sm3;                 // [32][36]
    float* Xs  = Rs + 32 * 36;        // [32][132]
    float* XiS = Xs + 32 * 132;       // [32][132]
    float* Ag  = XiS + 32 * 132;      // [32][132]

    const int b = blockIdx.y;
    const int it0 = blockIdx.x * 32;
    const int tid = threadIdx.x;
    const int ti = tid >> 3;          // local i (0..31)
    const int tg = tid & 7;           // d-group
    const int d0 = tg * 16;
    const float* xb = x + (size_t)b * NN * DD;

    // stage x rows of this i-tile
    #pragma unroll
    for (int k = 0; k < 4; k++) {
        int r = tid >> 3, c4 = (tid & 7) + k * 8;
        ((float4*)(XiS + r * 132))[c4] = ((const float4*)(xb + (size_t)(it0 + r) * DD))[c4];
    }

    float acc[16];
    #pragma unroll
    for (int k = 0; k < 16; k++) acc[k] = 0.f;

    for (int jc = 0; jc < NN; jc += 32) {
        __syncthreads();
        {   // R chunk: rows jc..jc+31, cols it0..it0+31
            int jr = tid >> 3, ic4 = tid & 7;
            ((float4*)(Rs + jr * 36))[ic4] =
                ((const float4*)(d_logits + ((size_t)b * NN + jc + jr) * NN + it0))[ic4];
        }
        #pragma unroll
        for (int k = 0; k < 4; k++) {
            int r = tid >> 3, c4 = (tid & 7) + k * 8;
            ((float4*)(Xs + r * 132))[c4] = ((const float4*)(xb + (size_t)(jc + r) * DD))[c4];
        }
        __syncthreads();
        #pragma unroll 4
        for (int j = 0; j < 32; j++) {
            float rv = Rs[j * 36 + ti];
            const float4* xr = (const float4*)(Xs + j * 132 + d0);
            float4 x0 = xr[0], x1 = xr[1], x2 = xr[2], x3 = xr[3];
            acc[0]  += rv * x0.x; acc[1]  += rv * x0.y; acc[2]  += rv * x0.z; acc[3]  += rv * x0.w;
            acc[4]  += rv * x1.x; acc[5]  += rv * x1.y; acc[6]  += rv * x1.z; acc[7]  += rv * x1.w;
            acc[8]  += rv * x2.x; acc[9]  += rv * x2.y; acc[10] += rv * x2.z; acc[11] += rv * x2.w;
            acc[12] += rv * x3.x; acc[13] += rv * x3.y; acc[14] += rv * x3.z; acc[15] += rv * x3.w;
        }
    }
    __syncthreads();
    #pragma unroll
    for (int k = 0; k < 16; k++) Ag[ti * 132 + d0 + k] = acc[k];
    __syncthreads();

    // h = Ag @ pwa_w + XiS @ pwoa_w + biases
    float h[16];
    #pragma unroll
    for (int k = 0; k < 16; k++) h[k] = pwa_b[d0 + k] + pwoa_b[d0 + k];
    for (int k = 0; k < DD; k++) {
        float a  = Ag[ti * 132 + k];
        float xv = XiS[ti * 132 + k];
        const float4* pa = (const float4*)(pwa_w + (size_t)k * DD + d0);
        const float4* po = (const float4*)(pwoa_w + (size_t)k * DD + d0);
        #pragma unroll
        for (int q = 0; q < 4; q++) {
            float4 A4 = pa[q], O4 = po[q];
            h[q * 4 + 0] += a * A4.x + xv * O4.x;
            h[q * 4 + 1] += a * A4.y + xv * O4.y;
            h[q * 4 + 2] += a * A4.z + xv * O4.z;
            h[q * 4 + 3] += a * A4.w + xv * O4.w;
        }
    }

    // BN (eval) + selu + store + pool score partial
    const float SELU_S = 1.0507009873554805f;
    const float SELU_A = 1.6732632423543772f;
    float p = 0.f;
    #pragma unroll
    for (int k = 0; k < 16; k++) {
        int d = d0 + k;
        float sc = bn_g[d] * rsqrtf(bn_v[d] + 1e-5f);
        float hv = (h[k] - bn_m[d]) * sc + bn_b[d];
        hv = (hv > 0.f) ? SELU_S * hv : SELU_S * SELU_A * (expf(hv) - 1.f);
        d_h[((size_t)b * NN + it0 + ti) * DD + d] = hv;
        p += hv * pool_w[d];
    }
    #pragma unroll
    for (int o = 4; o > 0; o >>= 1) p += __shfl_xor_sync(0xffffffffu, p, o);
    if (tg == 0) {
        float sg = 1.f / (1.f + expf(-(p + pool_b[0])));
        d_scores[b * NN + it0 + ti] = sg;
    }
}

// ============================================================================
// Kernel 4: per batch: sort (score desc, idx asc), gather top 128 of h*score.
// ============================================================================
__global__ void __launch_bounds__(256)
k4_topk(float* __restrict__ out) {
    const int b = blockIdx.x;
    const int tid = threadIdx.x;
    __shared__ unsigned long long key[NN];

    float s = d_scores[b * NN + tid];
    unsigned u = __float_as_uint(s);
    u = (u & 0x80000000u) ? ~u : (u | 0x80000000u);  // ascending-order transform
    u = ~u;                                          // descending by score
    key[tid] = ((unsigned long long)u << 32) | (unsigned)tid;
    __syncthreads();

    // bitonic sort, ascending on the 64-bit key
    for (int k = 2; k <= NN; k <<= 1) {
        for (int j = k >> 1; j > 0; j >>= 1) {
            int ixj = tid ^ j;
            if (ixj > tid) {
                bool up = ((tid & k) == 0);
                unsigned long long a = key[tid], c = key[ixj];
                if ((a > c) == up) { key[tid] = c; key[ixj] = a; }
            }
            __syncthreads();
        }
    }

    for (int e = tid; e < KP * DD; e += 256) {
        int r = e >> 7;
        int d = e & 127;
        int j = (int)(key[r] & 0xFFFFFFFFu);
        float sv = d_scores[b * NN + j];
        out[((size_t)b * KP + r) * DD + d] = d_h[((size_t)b * NN + j) * DD + d] * sv;
    }
}

// ============================================================================
extern "C" void kernel_launch(void* const* d_in, const int* in_sizes, int n_in,
                              void* d_out, int out_size) {
    const float* x        = (const float*)d_in[0];
    const float* apw      = (const float*)d_in[1];
    const float* apb      = (const float*)d_in[2];
    const float* aweight  = (const float*)d_in[3];
    const float* pwa_w    = (const float*)d_in[4];
    const float* pwa_b    = (const float*)d_in[5];
    const float* pwoa_w   = (const float*)d_in[6];
    const float* pwoa_b   = (const float*)d_in[7];
    const float* bn_g     = (const float*)d_in[8];
    const float* bn_b     = (const float*)d_in[9];
    const float* bn_m     = (const float*)d_in[10];
    const float* bn_v     = (const float*)d_in[11];
    const float* pool_w   = (const float*)d_in[12];
    const float* pool_b   = (const float*)d_in[13];
    float* out = (float*)d_out;

    cudaFuncSetAttribute(k1_logits, cudaFuncAttributeMaxDynamicSharedMemorySize, SMEM1);
    cudaFuncSetAttribute(k3_agg_h,  cudaFuncAttributeMaxDynamicSharedMemorySize, SMEM3);

    k1_logits<<<dim3(NN, BB), 256, SMEM1>>>(x, apw, apb, aweight);
    k2_softmax<<<dim3(NN, BB), 256>>>();
    k3_agg_h<<<dim3(NN / 32, BB), 256, SMEM3>>>(x, pwa_w, pwa_b, pwoa_w, pwoa_b,
                                                bn_g, bn_b, bn_m, bn_v, pool_w, pool_b);
    k4_topk<<<BB, 256>>>(out);
}

// round 5
// speedup vs baseline: 2.2928x; 2.2928x over previous
#include <cuda_runtime.h>
#include <math.h>
#include <stdint.h>

#define BB 16
#define NN 256
#define DD 128
#define KP 128

// -------- scratch (device globals; no allocation allowed) --------
__device__ float    d_logits[(size_t)BB * NN * NN];   // 4 MB
__device__ float    d_h[(size_t)BB * NN * DD];        // 2 MB
__device__ float    d_scores[BB * NN];
__device__ int      d_perm[BB * KP];
__device__ uint32_t d_wbh[DD * 64];                   // W^T hi bf16x2 pairs [c][p]
__device__ uint32_t d_wbl[DD * 64];                   // W^T lo bf16x2 pairs [c][p]

__device__ __forceinline__ float tanh_approx(float x) {
    float y; asm("tanh.approx.f32 %0, %1;" : "=f"(y) : "f"(x)); return y;
}
// pack two floats to bf16x2: lo element = first arg (even index), hi = second
__device__ __forceinline__ uint32_t pack_bf16x2(float e0, float e1) {
    uint32_t u;
    asm("cvt.rn.bf16x2.f32 %0, %1, %2;" : "=r"(u) : "f"(e1), "f"(e0));
    return u;
}

// m16n8k16 bf16 mma: acc += A*B (fp32 acc, in place)
__device__ __forceinline__ void mma_bf16(float* c, const uint32_t* a,
                                         uint32_t b0, uint32_t b1) {
    asm volatile(
        "mma.sync.aligned.m16n8k16.row.col.f32.bf16.bf16.f32 "
        "{%0,%1,%2,%3}, {%4,%5,%6,%7}, {%8,%9}, {%0,%1,%2,%3};"
        : "+f"(c[0]), "+f"(c[1]), "+f"(c[2]), "+f"(c[3])
        : "r"(a[0]), "r"(a[1]), "r"(a[2]), "r"(a[3]), "r"(b0), "r"(b1));
}

#define PPAD 68
// smem: Ah, Al, Bh, Bl each [128][PPAD] uint; + XI/BSs/VS (128 f) + PART (256 f)
#define SMEM1_REQ (4 * 128 * PPAD * 4 + (128 * 3 + 256) * 4)

// ============================================================================
// Kernel 0: split W^T into bf16 hi/lo pair images.
// slot (c, p): d0=2p, d1=2p+1; value pair (W[d0][c], W[d1][c]).
// ============================================================================
__global__ void k0_wsplit(const float* __restrict__ W) {
    int idx = blockIdx.x * 256 + threadIdx.x;   // 0..8191
    int c = idx >> 6;
    int p = idx & 63;
    float w0 = W[(size_t)(2 * p) * DD + c];
    float w1 = W[(size_t)(2 * p + 1) * DD + c];
    uint32_t hi = pack_bf16x2(w0, w1);
    float r0 = w0 - __uint_as_float(hi << 16);
    float r1 = w1 - __uint_as_float(hi & 0xffff0000u);
    d_wbh[c * 64 + p] = hi;
    d_wbl[c * 64 + p] = pack_bf16x2(r0, r1);
}

// ============================================================================
// Kernel 1: per block (i,b):
//   D[j,c] = sum_d (x_j[d]*x_i[d]) * W^T[c][d]   via bf16x3 emulated-fp32 mma
//   logits[b,i,j] = sum_c v[c] * tanh(D[j,c] + bias[c])
// 8 warps: warp = (mt2 = wid&3 -> 32 j-rows) x (nh = wid>>2 -> 64 c-cols).
// ============================================================================
__global__ void __launch_bounds__(256, 1)
k1_mma(const float* __restrict__ x, const float* __restrict__ bias,
       const float* __restrict__ v) {
    extern __shared__ uint32_t sm[];
    uint32_t* Ah = sm;                       // [128][PPAD] hi pairs of y
    uint32_t* Al = Ah + 128 * PPAD;          // lo
    uint32_t* Bh = Al + 128 * PPAD;          // [128][PPAD] hi pairs of W^T
    uint32_t* Bl = Bh + 128 * PPAD;
    float* XI   = (float*)(Bl + 128 * PPAD); // [128]
    float* BSs  = XI + 128;
    float* VS   = BSs + 128;
    float* PART = VS + 128;                  // [256]

    const int b = blockIdx.y, i = blockIdx.x;
    const int tid = threadIdx.x;
    const int wid = tid >> 5, lid = tid & 31;
    const int g = lid >> 2, tig = lid & 3;
    const int mt2 = wid & 3, nh = wid >> 2;
    const float* xb = x + (size_t)b * NN * DD;

    if (tid < 128) {
        XI[tid]  = xb[(size_t)i * DD + tid];
        BSs[tid] = bias[tid];
        VS[tid]  = v[tid];
    }
    // stage W^T hi/lo into padded smem: 2048 uint4 each
    #pragma unroll
    for (int k = 0; k < 8; k++) {
        int e = tid + k * 256;              // uint4 index, 0..2047
        int r = e >> 4, c4 = e & 15;        // 16 uint4 per 64-uint row
        ((uint4*)(Bh + r * PPAD))[c4] = ((const uint4*)d_wbh)[e];
        ((uint4*)(Bl + r * PPAD))[c4] = ((const uint4*)d_wbl)[e];
    }
    __syncthreads();

    for (int t = 0; t < 2; t++) {
        const int j0 = t * 128;

        // build A hi/lo: y = x[j0+r][d] * x_i[d]; thread = (row r, 64-d half)
        {
            int r  = tid >> 1;
            int dg = (tid & 1) * 64;
            const float4* xr  = (const float4*)(xb + (size_t)(j0 + r) * DD + dg);
            const float4* xi4 = (const float4*)(XI + dg);
            uint32_t* ahr = Ah + r * PPAD + (dg >> 1);
            uint32_t* alr = Al + r * PPAD + (dg >> 1);
            #pragma unroll
            for (int q = 0; q < 16; q++) {
                float4 xv = xr[q], iv = xi4[q];
                float y0 = xv.x * iv.x, y1 = xv.y * iv.y;
                float y2 = xv.z * iv.z, y3 = xv.w * iv.w;
                uint32_t h0 = pack_bf16x2(y0, y1);
                uint32_t h1 = pack_bf16x2(y2, y3);
                float r0 = y0 - __uint_as_float(h0 << 16);
                float r1 = y1 - __uint_as_float(h0 & 0xffff0000u);
                float r2 = y2 - __uint_as_float(h1 << 16);
                float r3 = y3 - __uint_as_float(h1 & 0xffff0000u);
                ahr[q * 2]     = h0;
                ahr[q * 2 + 1] = h1;
                alr[q * 2]     = pack_bf16x2(r0, r1);
                alr[q * 2 + 1] = pack_bf16x2(r2, r3);
            }
        }
        __syncthreads();

        float acc[2][8][4];
        #pragma unroll
        for (int m = 0; m < 2; m++)
            #pragma unroll
            for (int n = 0; n < 8; n++)
                #pragma unroll
                for (int q = 0; q < 4; q++) acc[m][n][q] = 0.f;

        #pragma unroll
        for (int k = 0; k < 8; k++) {       // k16 steps over d
            uint32_t ah[2][4], al[2][4];
            #pragma unroll
            for (int m = 0; m < 2; m++) {
                const uint32_t* aph = Ah + (mt2 * 32 + m * 16 + g) * PPAD + k * 8 + tig;
                const uint32_t* apl = Al + (mt2 * 32 + m * 16 + g) * PPAD + k * 8 + tig;
                ah[m][0] = aph[0];            ah[m][1] = aph[8 * PPAD];
                ah[m][2] = aph[4];            ah[m][3] = aph[8 * PPAD + 4];
                al[m][0] = apl[0];            al[m][1] = apl[8 * PPAD];
                al[m][2] = apl[4];            al[m][3] = apl[8 * PPAD + 4];
            }
            #pragma unroll
            for (int nf = 0; nf < 8; nf++) {
                const uint32_t* bph = Bh + (nh * 64 + nf * 8 + g) * PPAD + k * 8 + tig;
                const uint32_t* bpl = Bl + (nh * 64 + nf * 8 + g) * PPAD + k * 8 + tig;
                uint32_t bh0 = bph[0], bh1 = bph[4];
                uint32_t bl0 = bpl[0], bl1 = bpl[4];
                mma_bf16(acc[0][nf], ah[0], bh0, bh1);
                mma_bf16(acc[1][nf], ah[1], bh0, bh1);
                mma_bf16(acc[0][nf], ah[0], bl0, bl1);
                mma_bf16(acc[1][nf], ah[1], bl0, bl1);
                mma_bf16(acc[0][nf], al[0], bh0, bh1);
                mma_bf16(acc[1][nf], al[1], bh0, bh1);
            }
        }

        // epilogue: tanh + v-dot, reduce over c
        float prt[4] = {0.f, 0.f, 0.f, 0.f};
        #pragma unroll
        for (int m = 0; m < 2; m++) {
            #pragma unroll
            for (int nf = 0; nf < 8; nf++) {
                int c0 = nh * 64 + nf * 8 + 2 * tig;
                float v0 = VS[c0], v1 = VS[c0 + 1];
                float b0 = BSs[c0], b1 = BSs[c0 + 1];
                prt[2 * m + 0] += v0 * tanh_approx(acc[m][nf][0] + b0)
                                + v1 * tanh_approx(acc[m][nf][1] + b1);
                prt[2 * m + 1] += v0 * tanh_approx(acc[m][nf][2] + b0)
                                + v1 * tanh_approx(acc[m][nf][3] + b1);
            }
        }
        #pragma unroll
        for (int o = 1; o <= 2; o <<= 1) {
            prt[0] += __shfl_xor_sync(0xffffffffu, prt[0], o);
            prt[1] += __shfl_xor_sync(0xffffffffu, prt[1], o);
            prt[2] += __shfl_xor_sync(0xffffffffu, prt[2], o);
            prt[3] += __shfl_xor_sync(0xffffffffu, prt[3], o);
        }
        if (tig == 0) {
            int base = nh * 128 + mt2 * 32;
            PART[base + g]      = prt[0];
            PART[base + g + 8]  = prt[1];
            PART[base + g + 16] = prt[2];
            PART[base + g + 24] = prt[3];
        }
        __syncthreads();
        if (tid < 128) {
            float lg = PART[tid] + PART[128 + tid];
            d_logits[((size_t)b * NN + i) * NN + j0 + tid] = lg;
        }
        __syncthreads();
    }
}

// ============================================================================
// Kernel 2: row softmax of d_logits in place (matrix symmetric -> row softmax
// of row j yields att[b,i,j] at [j][i]).
// ============================================================================
__global__ void __launch_bounds__(256)
k2_softmax() {
    const int b = blockIdx.y, r = blockIdx.x;
    float* row = d_logits + ((size_t)b * NN + r) * NN;
    const int tid = threadIdx.x;
    __shared__ float sred[8];
    __shared__ float sbc;

    float val = row[tid];
    float m = val;
    #pragma unroll
    for (int o = 16; o > 0; o >>= 1) m = fmaxf(m, __shfl_xor_sync(0xffffffffu, m, o));
    if ((tid & 31) == 0) sred[tid >> 5] = m;
    __syncthreads();
    float M = sred[0];
    #pragma unroll
    for (int w = 1; w < 8; w++) M = fmaxf(M, sred[w]);
    __syncthreads();

    float e = expf(val - M);
    float s = e;
    #pragma unroll
    for (int o = 16; o > 0; o >>= 1) s += __shfl_xor_sync(0xffffffffu, s, o);
    if ((tid & 31) == 0) sred[tid >> 5] = s;
    __syncthreads();
    if (tid == 0) {
        float S = 0.f;
        #pragma unroll
        for (int w = 0; w < 8; w++) S += sred[w];
        sbc = 1.f / S;
    }
    __syncthreads();
    row[tid] = e * sbc;
}

// ============================================================================
// Kernel 3: agg = R^T @ x ; h = agg@pwa_w + x@pwoa_w + b; BN; selu; pool score.
// ============================================================================
#define SMEM3 ((32 * 36 + 3 * 32 * 132) * 4)

__global__ void __launch_bounds__(256)
k3_agg_h(const float* __restrict__ x,
         const float* __restrict__ pwa_w, const float* __restrict__ pwa_b,
         const float* __restrict__ pwoa_w, const float* __restrict__ pwoa_b,
         const float* __restrict__ bn_g, const float* __restrict__ bn_b,
         const float* __restrict__ bn_m, const float* __restrict__ bn_v,
         const float* __restrict__ pool_w, const float* __restrict__ pool_b) {
    extern __shared__ float sm3[];
    float* Rs  = sm3;
    float* Xs  = Rs + 32 * 36;
    float* XiS = Xs + 32 * 132;
    float* Ag  = XiS + 32 * 132;

    const int b = blockIdx.y;
    const int it0 = blockIdx.x * 32;
    const int tid = threadIdx.x;
    const int ti = tid >> 3;
    const int tg = tid & 7;
    const int d0 = tg * 16;
    const float* xb = x + (size_t)b * NN * DD;

    #pragma unroll
    for (int k = 0; k < 4; k++) {
        int r = tid >> 3, c4 = (tid & 7) + k * 8;
        ((float4*)(XiS + r * 132))[c4] = ((const float4*)(xb + (size_t)(it0 + r) * DD))[c4];
    }

    float acc[16];
    #pragma unroll
    for (int k = 0; k < 16; k++) acc[k] = 0.f;

    for (int jc = 0; jc < NN; jc += 32) {
        __syncthreads();
        {
            int jr = tid >> 3, ic4 = tid & 7;
            ((float4*)(Rs + jr * 36))[ic4] =
                ((const float4*)(d_logits + ((size_t)b * NN + jc + jr) * NN + it0))[ic4];
        }
        #pragma unroll
        for (int k = 0; k < 4; k++) {
            int r = tid >> 3, c4 = (tid & 7) + k * 8;
            ((float4*)(Xs + r * 132))[c4] = ((const float4*)(xb + (size_t)(jc + r) * DD))[c4];
        }
        __syncthreads();
        #pragma unroll 4
        for (int j = 0; j < 32; j++) {
            float rv = Rs[j * 36 + ti];
            const float4* xr = (const float4*)(Xs + j * 132 + d0);
            float4 x0 = xr[0], x1 = xr[1], x2 = xr[2], x3 = xr[3];
            acc[0]  += rv * x0.x; acc[1]  += rv * x0.y; acc[2]  += rv * x0.z; acc[3]  += rv * x0.w;
            acc[4]  += rv * x1.x; acc[5]  += rv * x1.y; acc[6]  += rv * x1.z; acc[7]  += rv * x1.w;
            acc[8]  += rv * x2.x; acc[9]  += rv * x2.y; acc[10] += rv * x2.z; acc[11] += rv * x2.w;
            acc[12] += rv * x3.x; acc[13] += rv * x3.y; acc[14] += rv * x3.z; acc[15] += rv * x3.w;
        }
    }
    __syncthreads();
    #pragma unroll
    for (int k = 0; k < 16; k++) Ag[ti * 132 + d0 + k] = acc[k];
    __syncthreads();

    float h[16];
    #pragma unroll
    for (int k = 0; k < 16; k++) h[k] = pwa_b[d0 + k] + pwoa_b[d0 + k];
    for (int k = 0; k < DD; k++) {
        float a  = Ag[ti * 132 + k];
        float xv = XiS[ti * 132 + k];
        const float4* pa = (const float4*)(pwa_w + (size_t)k * DD + d0);
        const float4* po = (const float4*)(pwoa_w + (size_t)k * DD + d0);
        #pragma unroll
        for (int q = 0; q < 4; q++) {
            float4 A4 = pa[q], O4 = po[q];
            h[q * 4 + 0] += a * A4.x + xv * O4.x;
            h[q * 4 + 1] += a * A4.y + xv * O4.y;
            h[q * 4 + 2] += a * A4.z + xv * O4.z;
            h[q * 4 + 3] += a * A4.w + xv * O4.w;
        }
    }

    const float SELU_S = 1.0507009873554805f;
    const float SELU_A = 1.6732632423543772f;
    float p = 0.f;
    #pragma unroll
    for (int k = 0; k < 16; k++) {
        int d = d0 + k;
        float sc = bn_g[d] * rsqrtf(bn_v[d] + 1e-5f);
        float hv = (h[k] - bn_m[d]) * sc + bn_b[d];
        hv = (hv > 0.f) ? SELU_S * hv : SELU_S * SELU_A * (expf(hv) - 1.f);
        d_h[((size_t)b * NN + it0 + ti) * DD + d] = hv;
        p += hv * pool_w[d];
    }
    #pragma unroll
    for (int o = 4; o > 0; o >>= 1) p += __shfl_xor_sync(0xffffffffu, p, o);
    if (tg == 0) {
        float sg = 1.f / (1.f + expf(-(p + pool_b[0])));
        d_scores[b * NN + it0 + ti] = sg;
    }
}

// ============================================================================
// Kernel 4a: per-batch bitonic sort (score desc, idx asc) -> d_perm
// ============================================================================
__global__ void __launch_bounds__(256)
k4a_sort() {
    const int b = blockIdx.x;
    const int tid = threadIdx.x;
    __shared__ unsigned long long key[NN];

    float s = d_scores[b * NN + tid];
    unsigned u = __float_as_uint(s);
    u = (u & 0x80000000u) ? ~u : (u | 0x80000000u);
    u = ~u;
    key[tid] = ((unsigned long long)u << 32) | (unsigned)tid;
    __syncthreads();

    for (int k = 2; k <= NN; k <<= 1) {
        for (int j = k >> 1; j > 0; j >>= 1) {
            int ixj = tid ^ j;
            if (ixj > tid) {
                bool up = ((tid & k) == 0);
                unsigned long long a = key[tid], c = key[ixj];
                if ((a > c) == up) { key[tid] = c; key[ixj] = a; }
            }
            __syncthreads();
        }
    }
    if (tid < KP) d_perm[b * KP + tid] = (int)(key[tid] & 0xFFFFFFFFu);
}

// ============================================================================
// Kernel 4b: gather out[b,r,:] = h[b,perm[r],:] * score[b,perm[r]]
// ============================================================================
__global__ void __launch_bounds__(256)
k4b_gather(float* __restrict__ out) {
    const int b = blockIdx.y;
    const int r = blockIdx.x * 8 + (threadIdx.x >> 5);
    const int lane = threadIdx.x & 31;
    int j = d_perm[b * KP + r];
    float sv = d_scores[b * NN + j];
    const float4* src = (const float4*)(d_h + ((size_t)b * NN + j) * DD);
    float4* dst = (float4*)(out + ((size_t)b * KP + r) * DD);
    float4 v = src[lane];
    dst[lane] = make_float4(v.x * sv, v.y * sv, v.z * sv, v.w * sv);
}

// ============================================================================
extern "C" void kernel_launch(void* const* d_in, const int* in_sizes, int n_in,
                              void* d_out, int out_size) {
    const float* x        = (const float*)d_in[0];
    const float* apw      = (const float*)d_in[1];
    const float* apb      = (const float*)d_in[2];
    const float* aweight  = (const float*)d_in[3];
    const float* pwa_w    = (const float*)d_in[4];
    const float* pwa_b    = (const float*)d_in[5];
    const float* pwoa_w   = (const float*)d_in[6];
    const float* pwoa_b   = (const float*)d_in[7];
    const float* bn_g     = (const float*)d_in[8];
    const float* bn_b     = (const float*)d_in[9];
    const float* bn_m     = (const float*)d_in[10];
    const float* bn_v     = (const float*)d_in[11];
    const float* pool_w   = (const float*)d_in[12];
    const float* pool_b   = (const float*)d_in[13];
    float* out = (float*)d_out;

    cudaFuncSetAttribute(k1_mma, cudaFuncAttributeMaxDynamicSharedMemorySize, SMEM1_REQ);
    cudaFuncSetAttribute(k3_agg_h, cudaFuncAttributeMaxDynamicSharedMemorySize, SMEM3);

    k0_wsplit<<<32, 256>>>(apw);
    k1_mma<<<dim3(NN, BB), 256, SMEM1_REQ>>>(x, apb, aweight);
    k2_softmax<<<dim3(NN, BB), 256>>>();
    k3_agg_h<<<dim3(NN / 32, BB), 256, SMEM3>>>(x, pwa_w, pwa_b, pwoa_w, pwoa_b,
                                                bn_g, bn_b, bn_m, bn_v, pool_w, pool_b);
    k4a_sort<<<BB, 256>>>();
    k4b_gather<<<dim3(16, BB), 256>>>(out);
}

// round 6
// speedup vs baseline: 3.1903x; 1.3914x over previous
#include <cuda_runtime.h>
#include <math.h>
#include <stdint.h>

#define BB 16
#define NN 256
#define DD 128
#define KP 128
#define LOG2E 1.4426950408889634f

// -------- scratch (device globals; no allocation allowed) --------
__device__ float    d_logits[(size_t)BB * NN * NN];   // 4 MB (raw logits)
__device__ float    d_h[(size_t)BB * NN * DD];        // 2 MB
__device__ float    d_scores[BB * NN];
__device__ float    d_rowM[BB * NN];                  // per-row max
__device__ float    d_rowIS[BB * NN];                 // per-row 1/sum(exp)
__device__ int      d_perm[BB * KP];
__device__ uint32_t d_wbh[DD * 64];                   // W^T hi bf16x2 pairs [c][p]
__device__ uint32_t d_wbl[DD * 64];                   // W^T lo bf16x2 pairs [c][p]

__device__ __forceinline__ float tanh_approx(float x) {
    float y; asm("tanh.approx.f32 %0, %1;" : "=f"(y) : "f"(x)); return y;
}
__device__ __forceinline__ uint32_t pack_bf16x2(float e0, float e1) {
    uint32_t u;
    asm("cvt.rn.bf16x2.f32 %0, %1, %2;" : "=r"(u) : "f"(e1), "f"(e0));
    return u;
}
__device__ __forceinline__ void mma_bf16(float* c, const uint32_t* a,
                                         uint32_t b0, uint32_t b1) {
    asm volatile(
        "mma.sync.aligned.m16n8k16.row.col.f32.bf16.bf16.f32 "
        "{%0,%1,%2,%3}, {%4,%5,%6,%7}, {%8,%9}, {%0,%1,%2,%3};"
        : "+f"(c[0]), "+f"(c[1]), "+f"(c[2]), "+f"(c[3])
        : "r"(a[0]), "r"(a[1]), "r"(a[2]), "r"(a[3]), "r"(b0), "r"(b1));
}

#define PPAD 68
// smem: Ah, Al, Bh, Bl each [128][PPAD]; XI[2][128]; BSs/VS 128 each; PART 256
#define SMEM1_REQ ((4 * 128 * PPAD + 256 + 128 * 2 + 256) * 4)

// ============================================================================
// Kernel 0: split W^T into bf16 hi/lo pair images.
// ============================================================================
__global__ void k0_wsplit(const float* __restrict__ W) {
    int idx = blockIdx.x * 256 + threadIdx.x;   // 0..8191
    int c = idx >> 6;
    int p = idx & 63;
    float w0 = W[(size_t)(2 * p) * DD + c];
    float w1 = W[(size_t)(2 * p + 1) * DD + c];
    uint32_t hi = pack_bf16x2(w0, w1);
    float r0 = w0 - __uint_as_float(hi << 16);
    float r1 = w1 - __uint_as_float(hi & 0xffff0000u);
    d_wbh[c * 64 + p] = hi;
    d_wbl[c * 64 + p] = pack_bf16x2(r0, r1);
}

// ============================================================================
// Kernel 1: symmetric-pair version. Block (p, b) owns i1=p and i2=255-p,
// computes the 3 necessary 128-j tile GEMMs (j >= i half only), writes both
// (i,j) and (j,i). bf16x3 emulated-fp32 mma.
// ============================================================================
__global__ void __launch_bounds__(256, 1)
k1_mma(const float* __restrict__ x, const float* __restrict__ bias,
       const float* __restrict__ v) {
    extern __shared__ uint32_t sm[];
    uint32_t* Ah = sm;                       // [128][PPAD]
    uint32_t* Al = Ah + 128 * PPAD;
    uint32_t* Bh = Al + 128 * PPAD;
    uint32_t* Bl = Bh + 128 * PPAD;
    float* XI   = (float*)(Bl + 128 * PPAD); // [2][128]
    float* BSs  = XI + 256;
    float* VS   = BSs + 128;
    float* PART = VS + 128;                  // [256]

    const int p = blockIdx.x, b = blockIdx.y;
    const int i1 = p, i2 = NN - 1 - p;
    const int tid = threadIdx.x;
    const int wid = tid >> 5, lid = tid & 31;
    const int g = lid >> 2, tig = lid & 3;
    const int mt2 = wid & 3, nh = wid >> 2;
    const float* xb = x + (size_t)b * NN * DD;

    if (tid < 128) {
        XI[tid]       = xb[(size_t)i1 * DD + tid];
        XI[128 + tid] = xb[(size_t)i2 * DD + tid];
        BSs[tid] = bias[tid];
        VS[tid]  = v[tid];
    }
    #pragma unroll
    for (int k = 0; k < 8; k++) {
        int e = tid + k * 256;
        int r = e >> 4, c4 = e & 15;
        ((uint4*)(Bh + r * PPAD))[c4] = ((const uint4*)d_wbh)[e];
        ((uint4*)(Bl + r * PPAD))[c4] = ((const uint4*)d_wbl)[e];
    }
    __syncthreads();

    // three tiles: (xi sel, j0, jmin within tile)
    const int t_xi[3]   = {0, 0, 1};
    const int t_j0[3]   = {0, 128, 128};
    const int t_jmin[3] = {p, 0, 127 - p};

    for (int tt = 0; tt < 3; tt++) {
        const int j0 = t_j0[tt];
        const float* xisel = XI + t_xi[tt] * 128;
        const int ii = t_xi[tt] ? i2 : i1;

        // build A hi/lo: y = x[j0+r][d] * xi[d]; thread = (row r, 64-d half)
        {
            int r  = tid >> 1;
            int dg = (tid & 1) * 64;
            const float4* xr  = (const float4*)(xb + (size_t)(j0 + r) * DD + dg);
            const float4* xi4 = (const float4*)(xisel + dg);
            uint32_t* ahr = Ah + r * PPAD + (dg >> 1);
            uint32_t* alr = Al + r * PPAD + (dg >> 1);
            #pragma unroll
            for (int q = 0; q < 16; q++) {
                float4 xv = xr[q], iv = xi4[q];
                float y0 = xv.x * iv.x, y1 = xv.y * iv.y;
                float y2 = xv.z * iv.z, y3 = xv.w * iv.w;
                uint32_t h0 = pack_bf16x2(y0, y1);
                uint32_t h1 = pack_bf16x2(y2, y3);
                float r0 = y0 - __uint_as_float(h0 << 16);
                float r1 = y1 - __uint_as_float(h0 & 0xffff0000u);
                float r2 = y2 - __uint_as_float(h1 << 16);
                float r3 = y3 - __uint_as_float(h1 & 0xffff0000u);
                ahr[q * 2]     = h0;
                ahr[q * 2 + 1] = h1;
                alr[q * 2]     = pack_bf16x2(r0, r1);
                alr[q * 2 + 1] = pack_bf16x2(r2, r3);
            }
        }
        __syncthreads();

        float acc[2][8][4];
        #pragma unroll
        for (int m = 0; m < 2; m++)
            #pragma unroll
            for (int n = 0; n < 8; n++)
                #pragma unroll
                for (int q = 0; q < 4; q++) acc[m][n][q] = 0.f;

        #pragma unroll
        for (int k = 0; k < 8; k++) {
            uint32_t ah[2][4], al[2][4];
            #pragma unroll
            for (int m = 0; m < 2; m++) {
                const uint32_t* aph = Ah + (mt2 * 32 + m * 16 + g) * PPAD + k * 8 + tig;
                const uint32_t* apl = Al + (mt2 * 32 + m * 16 + g) * PPAD + k * 8 + tig;
                ah[m][0] = aph[0];            ah[m][1] = aph[8 * PPAD];
                ah[m][2] = aph[4];            ah[m][3] = aph[8 * PPAD + 4];
                al[m][0] = apl[0];            al[m][1] = apl[8 * PPAD];
                al[m][2] = apl[4];            al[m][3] = apl[8 * PPAD + 4];
            }
            #pragma unroll
            for (int nf = 0; nf < 8; nf++) {
                const uint32_t* bph = Bh + (nh * 64 + nf * 8 + g) * PPAD + k * 8 + tig;
                const uint32_t* bpl = Bl + (nh * 64 + nf * 8 + g) * PPAD + k * 8 + tig;
                uint32_t bh0 = bph[0], bh1 = bph[4];
                uint32_t bl0 = bpl[0], bl1 = bpl[4];
                mma_bf16(acc[0][nf], ah[0], bh0, bh1);
                mma_bf16(acc[1][nf], ah[1], bh0, bh1);
                mma_bf16(acc[0][nf], ah[0], bl0, bl1);
                mma_bf16(acc[1][nf], ah[1], bl0, bl1);
                mma_bf16(acc[0][nf], al[0], bh0, bh1);
                mma_bf16(acc[1][nf], al[1], bh0, bh1);
            }
        }

        float prt[4] = {0.f, 0.f, 0.f, 0.f};
        #pragma unroll
        for (int m = 0; m < 2; m++) {
            #pragma unroll
            for (int nf = 0; nf < 8; nf++) {
                int c0 = nh * 64 + nf * 8 + 2 * tig;
                float v0 = VS[c0], v1 = VS[c0 + 1];
                float b0 = BSs[c0], b1 = BSs[c0 + 1];
                prt[2 * m + 0] += v0 * tanh_approx(acc[m][nf][0] + b0)
                                + v1 * tanh_approx(acc[m][nf][1] + b1);
                prt[2 * m + 1] += v0 * tanh_approx(acc[m][nf][2] + b0)
                                + v1 * tanh_approx(acc[m][nf][3] + b1);
            }
        }
        #pragma unroll
        for (int o = 1; o <= 2; o <<= 1) {
            prt[0] += __shfl_xor_sync(0xffffffffu, prt[0], o);
            prt[1] += __shfl_xor_sync(0xffffffffu, prt[1], o);
            prt[2] += __shfl_xor_sync(0xffffffffu, prt[2], o);
            prt[3] += __shfl_xor_sync(0xffffffffu, prt[3], o);
        }
        if (tig == 0) {
            int base = nh * 128 + mt2 * 32;
            PART[base + g]      = prt[0];
            PART[base + g + 8]  = prt[1];
            PART[base + g + 16] = prt[2];
            PART[base + g + 24] = prt[3];
        }
        __syncthreads();
        if (tid < 128 && tid >= t_jmin[tt]) {
            float lg = PART[tid] + PART[128 + tid];
            int j = j0 + tid;
            d_logits[((size_t)b * NN + ii) * NN + j] = lg;   // row (i, j)
            d_logits[((size_t)b * NN + j) * NN + ii] = lg;   // mirror (j, i)
        }
        __syncthreads();
    }
}

// ============================================================================
// Kernel 2r: per-row max and 1/sum(exp) of raw logits (no 4MB rewrite).
// One warp per row; block = 8 rows.
// ============================================================================
__global__ void __launch_bounds__(256)
k2r_rowstat() {
    const int b = blockIdx.y;
    const int row = blockIdx.x * 8 + (threadIdx.x >> 5);
    const int lane = threadIdx.x & 31;
    const float* rp = d_logits + ((size_t)b * NN + row) * NN;

    float4 a0 = ((const float4*)rp)[lane * 2];
    float4 a1 = ((const float4*)rp)[lane * 2 + 1];
    float m = fmaxf(fmaxf(fmaxf(a0.x, a0.y), fmaxf(a0.z, a0.w)),
                    fmaxf(fmaxf(a1.x, a1.y), fmaxf(a1.z, a1.w)));
    #pragma unroll
    for (int o = 16; o > 0; o >>= 1) m = fmaxf(m, __shfl_xor_sync(0xffffffffu, m, o));

    float s = exp2f((a0.x - m) * LOG2E) + exp2f((a0.y - m) * LOG2E)
            + exp2f((a0.z - m) * LOG2E) + exp2f((a0.w - m) * LOG2E)
            + exp2f((a1.x - m) * LOG2E) + exp2f((a1.y - m) * LOG2E)
            + exp2f((a1.z - m) * LOG2E) + exp2f((a1.w - m) * LOG2E);
    #pragma unroll
    for (int o = 16; o > 0; o >>= 1) s += __shfl_xor_sync(0xffffffffu, s, o);

    if (lane == 0) {
        d_rowM[b * NN + row]  = m;
        d_rowIS[b * NN + row] = 1.f / s;
    }
}

// ============================================================================
// Kernel 3: agg = att^T-form @ x with on-the-fly softmax; h GEMMs; BN; selu;
// pool score. 512 threads for latency hiding. Block = (32 i-rows, b).
// thread = (ti = tid>>4 : i-row, tg = tid&15 : 8-float d-group).
// ============================================================================
#define SMEM3 ((32 * 36 + 3 * 32 * 132) * 4)

__global__ void __launch_bounds__(512, 1)
k3_agg_h(const float* __restrict__ x,
         const float* __restrict__ pwa_w, const float* __restrict__ pwa_b,
         const float* __restrict__ pwoa_w, const float* __restrict__ pwoa_b,
         const float* __restrict__ bn_g, const float* __restrict__ bn_b,
         const float* __restrict__ bn_m, const float* __restrict__ bn_v,
         const float* __restrict__ pool_w, const float* __restrict__ pool_b) {
    extern __shared__ float sm3[];
    float* Rs  = sm3;                 // [32][36]
    float* Xs  = Rs + 32 * 36;        // [32][132]
    float* XiS = Xs + 32 * 132;       // [32][132]
    float* Ag  = XiS + 32 * 132;      // [32][132]

    const int b = blockIdx.y;
    const int it0 = blockIdx.x * 32;
    const int tid = threadIdx.x;
    const int ti = tid >> 4;          // 0..31
    const int tg = tid & 15;          // 0..15
    const int d0 = tg * 8;
    const float* xb = x + (size_t)b * NN * DD;

    // stage x rows of this i-tile: 1024 float4 over 512 threads
    #pragma unroll
    for (int k = 0; k < 2; k++) {
        int e = tid + k * 512;
        int r = e >> 5, c4 = e & 31;
        ((float4*)(XiS + r * 132))[c4] = ((const float4*)(xb + (size_t)(it0 + r) * DD))[c4];
    }

    float acc[8];
    #pragma unroll
    for (int k = 0; k < 8; k++) acc[k] = 0.f;

    for (int jc = 0; jc < NN; jc += 32) {
        __syncthreads();
        // Rs: softmax applied on the fly (att value at [j][i])
        if (tid < 256) {
            int jr = tid >> 3, ic4 = tid & 7;
            int row = jc + jr;
            float M  = d_rowM[b * NN + row];
            float IS = d_rowIS[b * NN + row];
            float4 rv = ((const float4*)(d_logits + ((size_t)b * NN + row) * NN + it0))[ic4];
            float4 e4;
            e4.x = exp2f((rv.x - M) * LOG2E) * IS;
            e4.y = exp2f((rv.y - M) * LOG2E) * IS;
            e4.z = exp2f((rv.z - M) * LOG2E) * IS;
            e4.w = exp2f((rv.w - M) * LOG2E) * IS;
            ((float4*)(Rs + jr * 36))[ic4] = e4;
        }
        // Xs: x rows jc..jc+31
        #pragma unroll
        for (int k = 0; k < 2; k++) {
            int e = tid + k * 512;
            int r = e >> 5, c4 = e & 31;
            ((float4*)(Xs + r * 132))[c4] = ((const float4*)(xb + (size_t)(jc + r) * DD))[c4];
        }
        __syncthreads();
        #pragma unroll 8
        for (int j = 0; j < 32; j++) {
            float rv = Rs[j * 36 + ti];
            const float4* xr = (const float4*)(Xs + j * 132 + d0);
            float4 x0 = xr[0], x1 = xr[1];
            acc[0] += rv * x0.x; acc[1] += rv * x0.y;
            acc[2] += rv * x0.z; acc[3] += rv * x0.w;
            acc[4] += rv * x1.x; acc[5] += rv * x1.y;
            acc[6] += rv * x1.z; acc[7] += rv * x1.w;
        }
    }
    __syncthreads();
    #pragma unroll
    for (int k = 0; k < 8; k++) Ag[ti * 132 + d0 + k] = acc[k];
    __syncthreads();

    // h = Ag @ pwa_w + XiS @ pwoa_w + biases
    float h[8];
    #pragma unroll
    for (int k = 0; k < 8; k++) h[k] = pwa_b[d0 + k] + pwoa_b[d0 + k];
    #pragma unroll 4
    for (int k = 0; k < DD; k++) {
        float a  = Ag[ti * 132 + k];
        float xv = XiS[ti * 132 + k];
        const float4* pa = (const float4*)(pwa_w + (size_t)k * DD + d0);
        const float4* po = (const float4*)(pwoa_w + (size_t)k * DD + d0);
        float4 A0 = pa[0], A1 = pa[1], O0 = po[0], O1 = po[1];
        h[0] += a * A0.x + xv * O0.x;
        h[1] += a * A0.y + xv * O0.y;
        h[2] += a * A0.z + xv * O0.z;
        h[3] += a * A0.w + xv * O0.w;
        h[4] += a * A1.x + xv * O1.x;
        h[5] += a * A1.y + xv * O1.y;
        h[6] += a * A1.z + xv * O1.z;
        h[7] += a * A1.w + xv * O1.w;
    }

    const float SELU_S = 1.0507009873554805f;
    const float SELU_A = 1.6732632423543772f;
    float p = 0.f;
    #pragma unroll
    for (int k = 0; k < 8; k++) {
        int d = d0 + k;
        float sc = bn_g[d] * rsqrtf(bn_v[d] + 1e-5f);
        float hv = (h[k] - bn_m[d]) * sc + bn_b[d];
        hv = (hv > 0.f) ? SELU_S * hv : SELU_S * SELU_A * (expf(hv) - 1.f);
        d_h[((size_t)b * NN + it0 + ti) * DD + d] = hv;
        p += hv * pool_w[d];
    }
    #pragma unroll
    for (int o = 8; o > 0; o >>= 1) p += __shfl_xor_sync(0xffffffffu, p, o);
    if (tg == 0) {
        float sg = 1.f / (1.f + expf(-(p + pool_b[0])));
        d_scores[b * NN + it0 + ti] = sg;
    }
}

// ============================================================================
// Kernel 4a: rank-based stable-descending top-k selection (O(N) per element).
// ============================================================================
__global__ void __launch_bounds__(256)
k4a_rank() {
    const int b = blockIdx.x;
    const int tid = threadIdx.x;
    __shared__ float ss[NN];

    float s = d_scores[b * NN + tid];
    ss[tid] = s;
    __syncthreads();

    int r = 0;
    #pragma unroll 16
    for (int j = 0; j < NN; j++) {
        float sj = ss[j];
        r += (sj > s) || (sj == s && j < tid);
    }
    if (r < KP) d_perm[b * KP + r] = tid;
}

// ============================================================================
// Kernel 4b: gather out[b,r,:] = h[b,perm[r],:] * score[b,perm[r]]
// ============================================================================
__global__ void __launch_bounds__(256)
k4b_gather(float* __restrict__ out) {
    const int b = blockIdx.y;
    const int r = blockIdx.x * 8 + (threadIdx.x >> 5);
    const int lane = threadIdx.x & 31;
    int j = d_perm[b * KP + r];
    float sv = d_scores[b * NN + j];
    const float4* src = (const float4*)(d_h + ((size_t)b * NN + j) * DD);
    float4* dst = (float4*)(out + ((size_t)b * KP + r) * DD);
    float4 v = src[lane];
    dst[lane] = make_float4(v.x * sv, v.y * sv, v.z * sv, v.w * sv);
}

// ============================================================================
extern "C" void kernel_launch(void* const* d_in, const int* in_sizes, int n_in,
                              void* d_out, int out_size) {
    const float* x        = (const float*)d_in[0];
    const float* apw      = (const float*)d_in[1];
    const float* apb      = (const float*)d_in[2];
    const float* aweight  = (const float*)d_in[3];
    const float* pwa_w    = (const float*)d_in[4];
    const float* pwa_b    = (const float*)d_in[5];
    const float* pwoa_w   = (const float*)d_in[6];
    const float* pwoa_b   = (const float*)d_in[7];
    const float* bn_g     = (const float*)d_in[8];
    const float* bn_b     = (const float*)d_in[9];
    const float* bn_m     = (const float*)d_in[10];
    const float* bn_v     = (const float*)d_in[11];
    const float* pool_w   = (const float*)d_in[12];
    const float* pool_b   = (const float*)d_in[13];
    float* out = (float*)d_out;

    cudaFuncSetAttribute(k1_mma, cudaFuncAttributeMaxDynamicSharedMemorySize, SMEM1_REQ);
    cudaFuncSetAttribute(k3_agg_h, cudaFuncAttributeMaxDynamicSharedMemorySize, SMEM3);

    k0_wsplit<<<32, 256>>>(apw);
    k1_mma<<<dim3(NN / 2, BB), 256, SMEM1_REQ>>>(x, apb, aweight);
    k2r_rowstat<<<dim3(NN / 8, BB), 256>>>();
    k3_agg_h<<<dim3(NN / 32, BB), 512, SMEM3>>>(x, pwa_w, pwa_b, pwoa_w, pwoa_b,
                                                bn_g, bn_b, bn_m, bn_v, pool_w, pool_b);
    k4a_rank<<<BB, 256>>>();
    k4b_gather<<<dim3(16, BB), 256>>>(out);
}

// round 7
// speedup vs baseline: 3.8885x; 1.2188x over previous
#include <cuda_runtime.h>
#include <math.h>
#include <stdint.h>

#define BB 16
#define NN 256
#define DD 128
#define KP 128
#define LOG2E 1.4426950408889634f

// -------- scratch (device globals; no allocation allowed) --------
__device__ float    d_logits[(size_t)BB * NN * NN];   // 4 MB (raw logits)
__device__ float    d_h[(size_t)BB * NN * DD];        // 2 MB
__device__ float    d_scores[BB * NN];
__device__ float    d_rowM[BB * NN];
__device__ float    d_rowIS[BB * NN];
__device__ int      d_perm[BB * KP];
__device__ uint32_t d_wbh[DD * 64];                   // W^T hi bf16x2 pairs [c][p]
__device__ uint32_t d_wbl[DD * 64];                   // W^T lo bf16x2 pairs [c][p]

__device__ __forceinline__ float tanh_approx(float x) {
    float y; asm("tanh.approx.f32 %0, %1;" : "=f"(y) : "f"(x)); return y;
}
__device__ __forceinline__ uint32_t pack_bf16x2(float e0, float e1) {
    uint32_t u;
    asm("cvt.rn.bf16x2.f32 %0, %1, %2;" : "=r"(u) : "f"(e1), "f"(e0));
    return u;
}
__device__ __forceinline__ void mma_bf16(float* c, const uint32_t* a,
                                         uint32_t b0, uint32_t b1) {
    asm volatile(
        "mma.sync.aligned.m16n8k16.row.col.f32.bf16.bf16.f32 "
        "{%0,%1,%2,%3}, {%4,%5,%6,%7}, {%8,%9}, {%0,%1,%2,%3};"
        : "+f"(c[0]), "+f"(c[1]), "+f"(c[2]), "+f"(c[3])
        : "r"(a[0]), "r"(a[1]), "r"(a[2]), "r"(a[3]), "r"(b0), "r"(b1));
}

#define PPAD 68
// smem: Ah/Al [64][PPAD], Bh/Bl [128][PPAD], XI[2][128], BSs, VS, PART[256]
#define SMEM1_REQ ((2 * 64 * PPAD + 2 * 128 * PPAD + 256 + 128 + 128 + 256) * 4)

// ============================================================================
// Kernel 0: split W^T into bf16 hi/lo pair images.
// ============================================================================
__global__ void k0_wsplit(const float* __restrict__ W) {
    int idx = blockIdx.x * 256 + threadIdx.x;   // 0..8191
    int c = idx >> 6;
    int p = idx & 63;
    float w0 = W[(size_t)(2 * p) * DD + c];
    float w1 = W[(size_t)(2 * p + 1) * DD + c];
    uint32_t hi = pack_bf16x2(w0, w1);
    float r0 = w0 - __uint_as_float(hi << 16);
    float r1 = w1 - __uint_as_float(hi & 0xffff0000u);
    d_wbh[c * 64 + p] = hi;
    d_wbl[c * 64 + p] = pack_bf16x2(r0, r1);
}

// ============================================================================
// Kernel 1: symmetric-pair, M=64 j-tiles, 2 CTAs/SM.
// Block (p,b) owns i1=p, i2=255-p. For each 64-row j-tile overlapping
// [i,255], compute D = (x_j . x_i) W^T via bf16x3 mma; logits via tanh+v-dot.
// Warp = (mt = wid&1 -> 32 rows) x (nq = wid>>1 -> 32 cols).
// ============================================================================
__global__ void __launch_bounds__(256, 2)
k1_mma(const float* __restrict__ x, const float* __restrict__ bias,
       const float* __restrict__ v) {
    extern __shared__ uint32_t sm[];
    uint32_t* Ah = sm;                        // [64][PPAD]
    uint32_t* Al = Ah + 64 * PPAD;
    uint32_t* Bh = Al + 64 * PPAD;            // [128][PPAD]
    uint32_t* Bl = Bh + 128 * PPAD;
    float* XI   = (float*)(Bl + 128 * PPAD);  // [2][128]
    float* BSs  = XI + 256;
    float* VS   = BSs + 128;
    float* PART = VS + 128;                   // [4][64]

    const int p = blockIdx.x, b = blockIdx.y;
    const int i1 = p, i2 = NN - 1 - p;
    const int tid = threadIdx.x;
    const int wid = tid >> 5, lid = tid & 31;
    const int g = lid >> 2, tig = lid & 3;
    const int mt = wid & 1, nq = wid >> 1;
    const float* xb = x + (size_t)b * NN * DD;

    if (tid < 128) {
        XI[tid]       = xb[(size_t)i1 * DD + tid];
        XI[128 + tid] = xb[(size_t)i2 * DD + tid];
        BSs[tid] = bias[tid];
        VS[tid]  = v[tid];
    }
    #pragma unroll
    for (int k = 0; k < 8; k++) {
        int e = tid + k * 256;
        int r = e >> 4, c4 = e & 15;
        ((uint4*)(Bh + r * PPAD))[c4] = ((const uint4*)d_wbh)[e];
        ((uint4*)(Bl + r * PPAD))[c4] = ((const uint4*)d_wbl)[e];
    }
    __syncthreads();

    for (int xi = 0; xi < 2; xi++) {
        const int ii = xi ? i2 : i1;
        const float* xisel = XI + xi * 128;
        for (int j0 = 0; j0 < NN; j0 += 64) {
            if (j0 + 63 < ii) continue;            // tile entirely below diagonal
            const int jmin = (ii > j0) ? (ii - j0) : 0;

            // build A hi/lo: y = x[j0+r][d]*xi[d]; thread=(row r, 32-d quarter)
            {
                int r  = tid >> 2;                 // 0..63
                int dg = (tid & 3) * 32;           // d start
                const float4* xr  = (const float4*)(xb + (size_t)(j0 + r) * DD + dg);
                const float4* xi4 = (const float4*)(xisel + dg);
                uint32_t* ahr = Ah + r * PPAD + (dg >> 1);
                uint32_t* alr = Al + r * PPAD + (dg >> 1);
                #pragma unroll
                for (int q = 0; q < 8; q++) {
                    float4 xv = xr[q], iv = xi4[q];
                    float y0 = xv.x * iv.x, y1 = xv.y * iv.y;
                    float y2 = xv.z * iv.z, y3 = xv.w * iv.w;
                    uint32_t h0 = pack_bf16x2(y0, y1);
                    uint32_t h1 = pack_bf16x2(y2, y3);
                    float r0 = y0 - __uint_as_float(h0 << 16);
                    float r1 = y1 - __uint_as_float(h0 & 0xffff0000u);
                    float r2 = y2 - __uint_as_float(h1 << 16);
                    float r3 = y3 - __uint_as_float(h1 & 0xffff0000u);
                    ahr[q * 2]     = h0;
                    ahr[q * 2 + 1] = h1;
                    alr[q * 2]     = pack_bf16x2(r0, r1);
                    alr[q * 2 + 1] = pack_bf16x2(r2, r3);
                }
            }
            __syncthreads();

            float acc[2][4][4];
            #pragma unroll
            for (int m = 0; m < 2; m++)
                #pragma unroll
                for (int n = 0; n < 4; n++)
                    #pragma unroll
                    for (int q = 0; q < 4; q++) acc[m][n][q] = 0.f;

            #pragma unroll
            for (int k = 0; k < 8; k++) {
                uint32_t ah[2][4], al[2][4];
                #pragma unroll
                for (int m = 0; m < 2; m++) {
                    const uint32_t* aph = Ah + (mt * 32 + m * 16 + g) * PPAD + k * 8 + tig;
                    const uint32_t* apl = Al + (mt * 32 + m * 16 + g) * PPAD + k * 8 + tig;
                    ah[m][0] = aph[0];            ah[m][1] = aph[8 * PPAD];
                    ah[m][2] = aph[4];            ah[m][3] = aph[8 * PPAD + 4];
                    al[m][0] = apl[0];            al[m][1] = apl[8 * PPAD];
                    al[m][2] = apl[4];            al[m][3] = apl[8 * PPAD + 4];
                }
                #pragma unroll
                for (int nf = 0; nf < 4; nf++) {
                    const uint32_t* bph = Bh + (nq * 32 + nf * 8 + g) * PPAD + k * 8 + tig;
                    const uint32_t* bpl = Bl + (nq * 32 + nf * 8 + g) * PPAD + k * 8 + tig;
                    uint32_t bh0 = bph[0], bh1 = bph[4];
                    uint32_t bl0 = bpl[0], bl1 = bpl[4];
                    mma_bf16(acc[0][nf], ah[0], bh0, bh1);
                    mma_bf16(acc[1][nf], ah[1], bh0, bh1);
                    mma_bf16(acc[0][nf], ah[0], bl0, bl1);
                    mma_bf16(acc[1][nf], ah[1], bl0, bl1);
                    mma_bf16(acc[0][nf], al[0], bh0, bh1);
                    mma_bf16(acc[1][nf], al[1], bh0, bh1);
                }
            }

            // epilogue: tanh + v-dot over this warp's 32 cols
            float prt[4] = {0.f, 0.f, 0.f, 0.f};
            #pragma unroll
            for (int m = 0; m < 2; m++) {
                #pragma unroll
                for (int nf = 0; nf < 4; nf++) {
                    int c0 = nq * 32 + nf * 8 + 2 * tig;
                    float v0 = VS[c0], v1 = VS[c0 + 1];
                    float b0 = BSs[c0], b1 = BSs[c0 + 1];
                    prt[2 * m + 0] += v0 * tanh_approx(acc[m][nf][0] + b0)
                                    + v1 * tanh_approx(acc[m][nf][1] + b1);
                    prt[2 * m + 1] += v0 * tanh_approx(acc[m][nf][2] + b0)
                                    + v1 * tanh_approx(acc[m][nf][3] + b1);
                }
            }
            #pragma unroll
            for (int o = 1; o <= 2; o <<= 1) {
                prt[0] += __shfl_xor_sync(0xffffffffu, prt[0], o);
                prt[1] += __shfl_xor_sync(0xffffffffu, prt[1], o);
                prt[2] += __shfl_xor_sync(0xffffffffu, prt[2], o);
                prt[3] += __shfl_xor_sync(0xffffffffu, prt[3], o);
            }
            if (tig == 0) {
                int base = nq * 64 + mt * 32;
                PART[base + g]      = prt[0];
                PART[base + g + 8]  = prt[1];
                PART[base + g + 16] = prt[2];
                PART[base + g + 24] = prt[3];
            }
            __syncthreads();
            if (tid < 64 && tid >= jmin) {
                float lg = PART[tid] + PART[64 + tid] + PART[128 + tid] + PART[192 + tid];
                int j = j0 + tid;
                d_logits[((size_t)b * NN + ii) * NN + j] = lg;
                d_logits[((size_t)b * NN + j) * NN + ii] = lg;
            }
            __syncthreads();
        }
    }
}

// ============================================================================
// Kernel 2r: per-row max and 1/sum(exp) (2 floats/row; no 4MB rewrite).
// ============================================================================
__global__ void __launch_bounds__(256)
k2r_rowstat() {
    const int b = blockIdx.y;
    const int row = blockIdx.x * 8 + (threadIdx.x >> 5);
    const int lane = threadIdx.x & 31;
    const float* rp = d_logits + ((size_t)b * NN + row) * NN;

    float4 a0 = ((const float4*)rp)[lane * 2];
    float4 a1 = ((const float4*)rp)[lane * 2 + 1];
    float m = fmaxf(fmaxf(fmaxf(a0.x, a0.y), fmaxf(a0.z, a0.w)),
                    fmaxf(fmaxf(a1.x, a1.y), fmaxf(a1.z, a1.w)));
    #pragma unroll
    for (int o = 16; o > 0; o >>= 1) m = fmaxf(m, __shfl_xor_sync(0xffffffffu, m, o));

    float s = exp2f((a0.x - m) * LOG2E) + exp2f((a0.y - m) * LOG2E)
            + exp2f((a0.z - m) * LOG2E) + exp2f((a0.w - m) * LOG2E)
            + exp2f((a1.x - m) * LOG2E) + exp2f((a1.y - m) * LOG2E)
            + exp2f((a1.z - m) * LOG2E) + exp2f((a1.w - m) * LOG2E);
    #pragma unroll
    for (int o = 16; o > 0; o >>= 1) s += __shfl_xor_sync(0xffffffffu, s, o);

    if (lane == 0) {
        d_rowM[b * NN + row]  = m;
        d_rowIS[b * NN + row] = 1.f / s;
    }
}

// ============================================================================
// Kernel 3: 16-row i-tiles (grid 256). agg with on-the-fly softmax; h GEMMs;
// BN; selu; pool score. Warp = one i-row; lane = 4-float d-group.
// ============================================================================
#define RSP 20
#define SMEM3 ((32 * RSP + 32 * 132 + 2 * 16 * 132) * 4)

__global__ void __launch_bounds__(512, 2)
k3_agg_h(const float* __restrict__ x,
         const float* __restrict__ pwa_w, const float* __restrict__ pwa_b,
         const float* __restrict__ pwoa_w, const float* __restrict__ pwoa_b,
         const float* __restrict__ bn_g, const float* __restrict__ bn_b,
         const float* __restrict__ bn_m, const float* __restrict__ bn_v,
         const float* __restrict__ pool_w, const float* __restrict__ pool_b) {
    extern __shared__ float sm3[];
    float* Rs  = sm3;                 // [32][RSP]
    float* Xs  = Rs + 32 * RSP;       // [32][132]
    float* XiS = Xs + 32 * 132;       // [16][132]
    float* Ag  = XiS + 16 * 132;      // [16][132]

    const int b = blockIdx.y;
    const int it0 = blockIdx.x * 16;
    const int tid = threadIdx.x;
    const int ti = tid >> 5;          // warp = i-row 0..15
    const int tg = tid & 31;          // lane = d-group
    const int d0 = tg * 4;
    const float* xb = x + (size_t)b * NN * DD;

    // stage x rows of this i-tile: 512 float4 over 512 threads
    {
        int r = tid >> 5, c4 = tid & 31;
        ((float4*)(XiS + r * 132))[c4] = ((const float4*)(xb + (size_t)(it0 + r) * DD))[c4];
    }

    float acc[4] = {0.f, 0.f, 0.f, 0.f};

    for (int jc = 0; jc < NN; jc += 32) {
        __syncthreads();
        // Rs: att values (softmax on the fly), rows jc..jc+31, cols it0..it0+15
        if (tid < 128) {
            int jr = tid >> 2, ic4 = tid & 3;
            int row = jc + jr;
            float M  = d_rowM[b * NN + row];
            float IS = d_rowIS[b * NN + row];
            float4 rv = ((const float4*)(d_logits + ((size_t)b * NN + row) * NN + it0))[ic4];
            float4 e4;
            e4.x = exp2f((rv.x - M) * LOG2E) * IS;
            e4.y = exp2f((rv.y - M) * LOG2E) * IS;
            e4.z = exp2f((rv.z - M) * LOG2E) * IS;
            e4.w = exp2f((rv.w - M) * LOG2E) * IS;
            ((float4*)(Rs + jr * RSP))[ic4] = e4;
        }
        // Xs: x rows jc..jc+31 (1024 float4)
        #pragma unroll
        for (int k = 0; k < 2; k++) {
            int e = tid + k * 512;
            int r = e >> 5, c4 = e & 31;
            ((float4*)(Xs + r * 132))[c4] = ((const float4*)(xb + (size_t)(jc + r) * DD))[c4];
        }
        __syncthreads();
        #pragma unroll 8
        for (int j = 0; j < 32; j++) {
            float rv = Rs[j * RSP + ti];
            float4 x4 = *(const float4*)(Xs + j * 132 + d0);
            acc[0] += rv * x4.x; acc[1] += rv * x4.y;
            acc[2] += rv * x4.z; acc[3] += rv * x4.w;
        }
    }
    __syncthreads();
    *(float4*)(Ag + ti * 132 + d0) = make_float4(acc[0], acc[1], acc[2], acc[3]);
    __syncthreads();

    // h = Ag @ pwa_w + XiS @ pwoa_w + biases
    float h[4];
    #pragma unroll
    for (int k = 0; k < 4; k++) h[k] = pwa_b[d0 + k] + pwoa_b[d0 + k];
    #pragma unroll 4
    for (int k = 0; k < DD; k++) {
        float a  = Ag[ti * 132 + k];
        float xv = XiS[ti * 132 + k];
        float4 A4 = *(const float4*)(pwa_w + (size_t)k * DD + d0);
        float4 O4 = *(const float4*)(pwoa_w + (size_t)k * DD + d0);
        h[0] += a * A4.x + xv * O4.x;
        h[1] += a * A4.y + xv * O4.y;
        h[2] += a * A4.z + xv * O4.z;
        h[3] += a * A4.w + xv * O4.w;
    }

    const float SELU_S = 1.0507009873554805f;
    const float SELU_A = 1.6732632423543772f;
    float p = 0.f;
    #pragma unroll
    for (int k = 0; k < 4; k++) {
        int d = d0 + k;
        float sc = bn_g[d] * rsqrtf(bn_v[d] + 1e-5f);
        float hv = (h[k] - bn_m[d]) * sc + bn_b[d];
        hv = (hv > 0.f) ? SELU_S * hv : SELU_S * SELU_A * (expf(hv) - 1.f);
        d_h[((size_t)b * NN + it0 + ti) * DD + d] = hv;
        p += hv * pool_w[d];
    }
    #pragma unroll
    for (int o = 16; o > 0; o >>= 1) p += __shfl_xor_sync(0xffffffffu, p, o);
    if (tg == 0) {
        float sg = 1.f / (1.f + expf(-(p + pool_b[0])));
        d_scores[b * NN + it0 + ti] = sg;
    }
}

// ============================================================================
// Kernel 4a: rank-based stable-descending top-k selection.
// ============================================================================
__global__ void __launch_bounds__(256)
k4a_rank() {
    const int b = blockIdx.x;
    const int tid = threadIdx.x;
    __shared__ float ss[NN];

    float s = d_scores[b * NN + tid];
    ss[tid] = s;
    __syncthreads();

    int r = 0;
    #pragma unroll 16
    for (int j = 0; j < NN; j++) {
        float sj = ss[j];
        r += (sj > s) || (sj == s && j < tid);
    }
    if (r < KP) d_perm[b * KP + r] = tid;
}

// ============================================================================
// Kernel 4b: gather out[b,r,:] = h[b,perm[r],:] * score[b,perm[r]]
// ============================================================================
__global__ void __launch_bounds__(256)
k4b_gather(float* __restrict__ out) {
    const int b = blockIdx.y;
    const int r = blockIdx.x * 8 + (threadIdx.x >> 5);
    const int lane = threadIdx.x & 31;
    int j = d_perm[b * KP + r];
    float sv = d_scores[b * NN + j];
    const float4* src = (const float4*)(d_h + ((size_t)b * NN + j) * DD);
    float4* dst = (float4*)(out + ((size_t)b * KP + r) * DD);
    float4 v = src[lane];
    dst[lane] = make_float4(v.x * sv, v.y * sv, v.z * sv, v.w * sv);
}

// ============================================================================
extern "C" void kernel_launch(void* const* d_in, const int* in_sizes, int n_in,
                              void* d_out, int out_size) {
    const float* x        = (const float*)d_in[0];
    const float* apw      = (const float*)d_in[1];
    const float* apb      = (const float*)d_in[2];
    const float* aweight  = (const float*)d_in[3];
    const float* pwa_w    = (const float*)d_in[4];
    const float* pwa_b    = (const float*)d_in[5];
    const float* pwoa_w   = (const float*)d_in[6];
    const float* pwoa_b   = (const float*)d_in[7];
    const float* bn_g     = (const float*)d_in[8];
    const float* bn_b     = (const float*)d_in[9];
    const float* bn_m     = (const float*)d_in[10];
    const float* bn_v     = (const float*)d_in[11];
    const float* pool_w   = (const float*)d_in[12];
    const float* pool_b   = (const float*)d_in[13];
    float* out = (float*)d_out;

    cudaFuncSetAttribute(k1_mma, cudaFuncAttributeMaxDynamicSharedMemorySize, SMEM1_REQ);
    cudaFuncSetAttribute(k3_agg_h, cudaFuncAttributeMaxDynamicSharedMemorySize, SMEM3);

    k0_wsplit<<<32, 256>>>(apw);
    k1_mma<<<dim3(NN / 2, BB), 256, SMEM1_REQ>>>(x, apb, aweight);
    k2r_rowstat<<<dim3(NN / 8, BB), 256>>>();
    k3_agg_h<<<dim3(NN / 16, BB), 512, SMEM3>>>(x, pwa_w, pwa_b, pwoa_w, pwoa_b,
                                                bn_g, bn_b, bn_m, bn_v, pool_w, pool_b);
    k4a_rank<<<BB, 256>>>();
    k4b_gather<<<dim3(16, BB), 256>>>(out);
}

// round 8
// speedup vs baseline: 4.3001x; 1.1058x over previous
#include <cuda_runtime.h>
#include <math.h>
#include <stdint.h>

#define BB 16
#define NN 256
#define DD 128
#define KP 128
#define LOG2E 1.4426950408889634f

// -------- scratch (device globals; no allocation allowed) --------
__device__ float    d_logits[(size_t)BB * NN * NN];   // 4 MB (raw logits)
__device__ float    d_h[(size_t)BB * NN * DD];        // 2 MB
__device__ float    d_scores[BB * NN];
__device__ float    d_rowM[BB * NN];
__device__ float    d_rowIS[BB * NN];
__device__ uint32_t d_wbh[DD * 64];                   // W^T hi bf16x2 pairs [c][p]
__device__ uint32_t d_wbl[DD * 64];
__device__ uint32_t d_pah[DD * 64], d_pal[DD * 64];   // pwa_w^T pairs [c][p over d]
__device__ uint32_t d_poh[DD * 64], d_pol[DD * 64];   // pwoa_w^T pairs
__device__ uint32_t d_xrh[BB * NN * 64];              // x row-major pairs [b][j][p over d]
__device__ uint32_t d_xrl[BB * NN * 64];
__device__ uint32_t d_xth[BB * DD * 128];             // x^T pairs [b][d][p over j]
__device__ uint32_t d_xtl[BB * DD * 128];
__device__ float    d_bnsc[DD], d_bnof[DD];           // folded BN scale/offset

__device__ __forceinline__ float tanh_approx(float x) {
    float y; asm("tanh.approx.f32 %0, %1;" : "=f"(y) : "f"(x)); return y;
}
__device__ __forceinline__ uint32_t pack_bf16x2(float e0, float e1) {
    uint32_t u;
    asm("cvt.rn.bf16x2.f32 %0, %1, %2;" : "=r"(u) : "f"(e1), "f"(e0));
    return u;
}
// split pair (a0,a1) into hi/lo bf16x2
__device__ __forceinline__ void split2(float a0, float a1, uint32_t& hi, uint32_t& lo) {
    hi = pack_bf16x2(a0, a1);
    float r0 = a0 - __uint_as_float(hi << 16);
    float r1 = a1 - __uint_as_float(hi & 0xffff0000u);
    lo = pack_bf16x2(r0, r1);
}
__device__ __forceinline__ void mma_bf16(float* c, const uint32_t* a,
                                         uint32_t b0, uint32_t b1) {
    asm volatile(
        "mma.sync.aligned.m16n8k16.row.col.f32.bf16.bf16.f32 "
        "{%0,%1,%2,%3}, {%4,%5,%6,%7}, {%8,%9}, {%0,%1,%2,%3};"
        : "+f"(c[0]), "+f"(c[1]), "+f"(c[2]), "+f"(c[3])
        : "r"(a[0]), "r"(a[1]), "r"(a[2]), "r"(a[3]), "r"(b0), "r"(b1));
}

// ============================================================================
// Kernel 0: all preprocessing splits.
//  blk [0,32):    W^T split (for k1)
//  blk [32,96):   pwa_w^T / pwoa_w^T splits
//  blk [96,1120): x row-major pair split
//  blk [1120,2144): x^T pair split
//  blk 2144:      BN fold
// ============================================================================
__global__ void k0_prep(const float* __restrict__ W, const float* __restrict__ x,
                        const float* __restrict__ pwa_w, const float* __restrict__ pwoa_w,
                        const float* __restrict__ pwa_b, const float* __restrict__ pwoa_b,
                        const float* __restrict__ bn_g, const float* __restrict__ bn_b,
                        const float* __restrict__ bn_m, const float* __restrict__ bn_v) {
    int blk = blockIdx.x, tid = threadIdx.x;
    if (blk < 32) {
        int idx = blk * 256 + tid;          // 0..8191
        int c = idx >> 6, p = idx & 63;
        uint32_t hi, lo;
        split2(W[(size_t)(2 * p) * DD + c], W[(size_t)(2 * p + 1) * DD + c], hi, lo);
        d_wbh[idx] = hi; d_wbl[idx] = lo;
    } else if (blk < 96) {
        int idx = (blk - 32) * 256 + tid;   // 0..16383
        int mat = idx >> 13;
        int r = idx & 8191;
        int c = r >> 6, p = r & 63;
        const float* src = mat ? pwoa_w : pwa_w;
        uint32_t hi, lo;
        split2(src[(size_t)(2 * p) * DD + c], src[(size_t)(2 * p + 1) * DD + c], hi, lo);
        if (mat) { d_poh[r] = hi; d_pol[r] = lo; }
        else     { d_pah[r] = hi; d_pal[r] = lo; }
    } else if (blk < 1120) {
        int idx = (blk - 96) * 256 + tid;   // 0..262143 = b*16384 + j*64 + p
        int p = idx & 63;
        const float* xp = x + (size_t)(idx >> 6) * DD;   // row (b*256+j)
        uint32_t hi, lo;
        split2(xp[2 * p], xp[2 * p + 1], hi, lo);
        d_xrh[idx] = hi; d_xrl[idx] = lo;
    } else if (blk < 2144) {
        int idx = (blk - 1120) * 256 + tid; // 0..262143 = b*16384 + d*128 + p
        int bb = idx >> 14;
        int d = (idx >> 7) & 127;
        int p = idx & 127;
        const float* xp = x + ((size_t)bb * NN + 2 * p) * DD + d;
        uint32_t hi, lo;
        split2(xp[0], xp[DD], hi, lo);
        d_xth[idx] = hi; d_xtl[idx] = lo;
    } else {
        if (tid < DD) {
            float sc = bn_g[tid] * rsqrtf(bn_v[tid] + 1e-5f);
            d_bnsc[tid] = sc;
            d_bnof[tid] = (pwa_b[tid] + pwoa_b[tid] - bn_m[tid]) * sc + bn_b[tid];
        }
    }
}

#define PPAD 68
// k1 smem: Ah/Al [64][PPAD], Bh/Bl [128][PPAD], XI[2][128], BSs, VS, PART[256]
#define SMEM1_REQ ((2 * 64 * PPAD + 2 * 128 * PPAD + 256 + 128 + 128 + 256) * 4)

// ============================================================================
// Kernel 1 (unchanged from R7): symmetric-pair, M=64 j-tiles, bf16x3 mma.
// ============================================================================
__global__ void __launch_bounds__(256, 2)
k1_mma(const float* __restrict__ x, const float* __restrict__ bias,
       const float* __restrict__ v) {
    extern __shared__ uint32_t sm[];
    uint32_t* Ah = sm;
    uint32_t* Al = Ah + 64 * PPAD;
    uint32_t* Bh = Al + 64 * PPAD;
    uint32_t* Bl = Bh + 128 * PPAD;
    float* XI   = (float*)(Bl + 128 * PPAD);
    float* BSs  = XI + 256;
    float* VS   = BSs + 128;
    float* PART = VS + 128;

    const int p = blockIdx.x, b = blockIdx.y;
    const int i1 = p, i2 = NN - 1 - p;
    const int tid = threadIdx.x;
    const int wid = tid >> 5, lid = tid & 31;
    const int g = lid >> 2, tig = lid & 3;
    const int mt = wid & 1, nq = wid >> 1;
    const float* xb = x + (size_t)b * NN * DD;

    if (tid < 128) {
        XI[tid]       = xb[(size_t)i1 * DD + tid];
        XI[128 + tid] = xb[(size_t)i2 * DD + tid];
        BSs[tid] = bias[tid];
        VS[tid]  = v[tid];
    }
    #pragma unroll
    for (int k = 0; k < 8; k++) {
        int e = tid + k * 256;
        int r = e >> 4, c4 = e & 15;
        ((uint4*)(Bh + r * PPAD))[c4] = ((const uint4*)d_wbh)[e];
        ((uint4*)(Bl + r * PPAD))[c4] = ((const uint4*)d_wbl)[e];
    }
    __syncthreads();

    for (int xi = 0; xi < 2; xi++) {
        const int ii = xi ? i2 : i1;
        const float* xisel = XI + xi * 128;
        for (int j0 = 0; j0 < NN; j0 += 64) {
            if (j0 + 63 < ii) continue;
            const int jmin = (ii > j0) ? (ii - j0) : 0;

            {
                int r  = tid >> 2;
                int dg = (tid & 3) * 32;
                const float4* xr  = (const float4*)(xb + (size_t)(j0 + r) * DD + dg);
                const float4* xi4 = (const float4*)(xisel + dg);
                uint32_t* ahr = Ah + r * PPAD + (dg >> 1);
                uint32_t* alr = Al + r * PPAD + (dg >> 1);
                #pragma unroll
                for (int q = 0; q < 8; q++) {
                    float4 xv = xr[q], iv = xi4[q];
                    uint32_t h0, l0, h1, l1;
                    split2(xv.x * iv.x, xv.y * iv.y, h0, l0);
                    split2(xv.z * iv.z, xv.w * iv.w, h1, l1);
                    ahr[q * 2]     = h0;
                    ahr[q * 2 + 1] = h1;
                    alr[q * 2]     = l0;
                    alr[q * 2 + 1] = l1;
                }
            }
            __syncthreads();

            float acc[2][4][4];
            #pragma unroll
            for (int m = 0; m < 2; m++)
                #pragma unroll
                for (int n = 0; n < 4; n++)
                    #pragma unroll
                    for (int q = 0; q < 4; q++) acc[m][n][q] = 0.f;

            #pragma unroll
            for (int k = 0; k < 8; k++) {
                uint32_t ah[2][4], al[2][4];
                #pragma unroll
                for (int m = 0; m < 2; m++) {
                    const uint32_t* aph = Ah + (mt * 32 + m * 16 + g) * PPAD + k * 8 + tig;
                    const uint32_t* apl = Al + (mt * 32 + m * 16 + g) * PPAD + k * 8 + tig;
                    ah[m][0] = aph[0];            ah[m][1] = aph[8 * PPAD];
                    ah[m][2] = aph[4];            ah[m][3] = aph[8 * PPAD + 4];
                    al[m][0] = apl[0];            al[m][1] = apl[8 * PPAD];
                    al[m][2] = apl[4];            al[m][3] = apl[8 * PPAD + 4];
                }
                #pragma unroll
                for (int nf = 0; nf < 4; nf++) {
                    const uint32_t* bph = Bh + (nq * 32 + nf * 8 + g) * PPAD + k * 8 + tig;
                    const uint32_t* bpl = Bl + (nq * 32 + nf * 8 + g) * PPAD + k * 8 + tig;
                    uint32_t bh0 = bph[0], bh1 = bph[4];
                    uint32_t bl0 = bpl[0], bl1 = bpl[4];
                    mma_bf16(acc[0][nf], ah[0], bh0, bh1);
                    mma_bf16(acc[1][nf], ah[1], bh0, bh1);
                    mma_bf16(acc[0][nf], ah[0], bl0, bl1);
                    mma_bf16(acc[1][nf], ah[1], bl0, bl1);
                    mma_bf16(acc[0][nf], al[0], bh0, bh1);
                    mma_bf16(acc[1][nf], al[1], bh0, bh1);
                }
            }

            float prt[4] = {0.f, 0.f, 0.f, 0.f};
            #pragma unroll
            for (int m = 0; m < 2; m++) {
                #pragma unroll
                for (int nf = 0; nf < 4; nf++) {
                    int c0 = nq * 32 + nf * 8 + 2 * tig;
                    float v0 = VS[c0], v1 = VS[c0 + 1];
                    float b0 = BSs[c0], b1 = BSs[c0 + 1];
                    prt[2 * m + 0] += v0 * tanh_approx(acc[m][nf][0] + b0)
                                    + v1 * tanh_approx(acc[m][nf][1] + b1);
                    prt[2 * m + 1] += v0 * tanh_approx(acc[m][nf][2] + b0)
                                    + v1 * tanh_approx(acc[m][nf][3] + b1);
                }
            }
            #pragma unroll
            for (int o = 1; o <= 2; o <<= 1) {
                prt[0] += __shfl_xor_sync(0xffffffffu, prt[0], o);
                prt[1] += __shfl_xor_sync(0xffffffffu, prt[1], o);
                prt[2] += __shfl_xor_sync(0xffffffffu, prt[2], o);
                prt[3] += __shfl_xor_sync(0xffffffffu, prt[3], o);
            }
            if (tig == 0) {
                int base = nq * 64 + mt * 32;
                PART[base + g]      = prt[0];
                PART[base + g + 8]  = prt[1];
                PART[base + g + 16] = prt[2];
                PART[base + g + 24] = prt[3];
            }
            __syncthreads();
            if (tid < 64 && tid >= jmin) {
                float lg = PART[tid] + PART[64 + tid] + PART[128 + tid] + PART[192 + tid];
                int j = j0 + tid;
                d_logits[((size_t)b * NN + ii) * NN + j] = lg;
                d_logits[((size_t)b * NN + j) * NN + ii] = lg;
            }
            __syncthreads();
        }
    }
}

// ============================================================================
// Kernel 2r: per-row max and 1/sum(exp).
// ============================================================================
__global__ void __launch_bounds__(256)
k2r_rowstat() {
    const int b = blockIdx.y;
    const int row = blockIdx.x * 8 + (threadIdx.x >> 5);
    const int lane = threadIdx.x & 31;
    const float* rp = d_logits + ((size_t)b * NN + row) * NN;

    float4 a0 = ((const float4*)rp)[lane * 2];
    float4 a1 = ((const float4*)rp)[lane * 2 + 1];
    float m = fmaxf(fmaxf(fmaxf(a0.x, a0.y), fmaxf(a0.z, a0.w)),
                    fmaxf(fmaxf(a1.x, a1.y), fmaxf(a1.z, a1.w)));
    #pragma unroll
    for (int o = 16; o > 0; o >>= 1) m = fmaxf(m, __shfl_xor_sync(0xffffffffu, m, o));

    float s = exp2f((a0.x - m) * LOG2E) + exp2f((a0.y - m) * LOG2E)
            + exp2f((a0.z - m) * LOG2E) + exp2f((a0.w - m) * LOG2E)
            + exp2f((a1.x - m) * LOG2E) + exp2f((a1.y - m) * LOG2E)
            + exp2f((a1.z - m) * LOG2E) + exp2f((a1.w - m) * LOG2E);
    #pragma unroll
    for (int o = 16; o > 0; o >>= 1) s += __shfl_xor_sync(0xffffffffu, s, o);

    if (lane == 0) {
        d_rowM[b * NN + row]  = m;
        d_rowIS[b * NN + row] = 1.f / s;
    }
}

// ============================================================================
// Kernel 3 (tensor-core): per CTA 32 i-rows.
// stage1: agg = att @ x (att built from logits + rowstats, bf16x3)
// stage2: h = [agg | x] @ [pwa^T ; pwoa^T] (bf16x3), then BN/selu/pool.
// 8 warps: warp w covers cols [16w, 16w+16); M=32 (2 m16 frags).
// ============================================================================
#define SMEM3 ((2 * 32 * PPAD + 2 * 128 * PPAD) * 4 + (32 * 132 + 256) * 4)

__global__ void __launch_bounds__(256, 2)
k3_tc(const float* __restrict__ pool_w, const float* __restrict__ pool_b) {
    extern __shared__ uint32_t sm3u[];
    uint32_t* Ah = sm3u;                       // [32][PPAD]
    uint32_t* Al = Ah + 32 * PPAD;
    uint32_t* Bh = Al + 32 * PPAD;             // [128][PPAD]
    uint32_t* Bl = Bh + 128 * PPAD;
    float* Ag   = (float*)(Bl + 128 * PPAD);   // [32][132]; doubles as Et
    float* PART = Ag + 32 * 132;               // [256]

    const int b = blockIdx.y;
    const int it0 = blockIdx.x * 32;
    const int tid = threadIdx.x;
    const int wid = tid >> 5, lid = tid & 31;
    const int g = lid >> 2, tig = lid & 3;

    float acc[2][2][4];
    #pragma unroll
    for (int m = 0; m < 2; m++)
        #pragma unroll
        for (int n = 0; n < 2; n++)
            #pragma unroll
            for (int q = 0; q < 4; q++) acc[m][n][q] = 0.f;

    // ---------------- stage 1: agg = att @ x ----------------
    for (int ch = 0; ch < 2; ch++) {
        const int j0 = ch * 128;
        // Et (in Ag buffer): att[i][j] for this chunk, transposed store
        #pragma unroll
        for (int k = 0; k < 4; k++) {
            int e = tid + k * 256;          // 1024 float4 loads
            int jr = e >> 3, ic4 = e & 7;
            int row = j0 + jr;
            float M  = d_rowM[b * NN + row];
            float IS = d_rowIS[b * NN + row];
            float4 rv = ((const float4*)(d_logits + ((size_t)b * NN + row) * NN + it0))[ic4];
            Ag[(ic4 * 4 + 0) * 132 + jr] = exp2f((rv.x - M) * LOG2E) * IS;
            Ag[(ic4 * 4 + 1) * 132 + jr] = exp2f((rv.y - M) * LOG2E) * IS;
            Ag[(ic4 * 4 + 2) * 132 + jr] = exp2f((rv.z - M) * LOG2E) * IS;
            Ag[(ic4 * 4 + 3) * 132 + jr] = exp2f((rv.w - M) * LOG2E) * IS;
        }
        __syncthreads();
        // A build from Et: pairs over j
        #pragma unroll
        for (int k = 0; k < 8; k++) {
            int e = tid + k * 256;          // 2048 pairs
            int i = e >> 6, pp = e & 63;
            float2 v2 = *(const float2*)(Ag + i * 132 + 2 * pp);
            uint32_t hi, lo;
            split2(v2.x, v2.y, hi, lo);
            Ah[i * PPAD + pp] = hi;
            Al[i * PPAD + pp] = lo;
        }
        // B copy: x^T pair slice [128 d][pairs ch*64 .. +64)
        #pragma unroll
        for (int k = 0; k < 8; k++) {
            int e = tid + k * 256;          // 2048 uint4
            int r = e >> 4, c4 = e & 15;
            ((uint4*)(Bh + r * PPAD))[c4] =
                ((const uint4*)(d_xth + ((size_t)b * DD + r) * 128 + ch * 64))[c4];
            ((uint4*)(Bl + r * PPAD))[c4] =
                ((const uint4*)(d_xtl + ((size_t)b * DD + r) * 128 + ch * 64))[c4];
        }
        __syncthreads();
        #pragma unroll
        for (int k = 0; k < 8; k++) {
            uint32_t ah[2][4], al[2][4];
            #pragma unroll
            for (int m = 0; m < 2; m++) {
                const uint32_t* aph = Ah + (m * 16 + g) * PPAD + k * 8 + tig;
                const uint32_t* apl = Al + (m * 16 + g) * PPAD + k * 8 + tig;
                ah[m][0] = aph[0];            ah[m][1] = aph[8 * PPAD];
                ah[m][2] = aph[4];            ah[m][3] = aph[8 * PPAD + 4];
                al[m][0] = apl[0];            al[m][1] = apl[8 * PPAD];
                al[m][2] = apl[4];            al[m][3] = apl[8 * PPAD + 4];
            }
            #pragma unroll
            for (int nf = 0; nf < 2; nf++) {
                const uint32_t* bph = Bh + (wid * 16 + nf * 8 + g) * PPAD + k * 8 + tig;
                const uint32_t* bpl = Bl + (wid * 16 + nf * 8 + g) * PPAD + k * 8 + tig;
                uint32_t bh0 = bph[0], bh1 = bph[4];
                uint32_t bl0 = bpl[0], bl1 = bpl[4];
                mma_bf16(acc[0][nf], ah[0], bh0, bh1);
                mma_bf16(acc[1][nf], ah[1], bh0, bh1);
                mma_bf16(acc[0][nf], ah[0], bl0, bl1);
                mma_bf16(acc[1][nf], ah[1], bl0, bl1);
                mma_bf16(acc[0][nf], al[0], bh0, bh1);
                mma_bf16(acc[1][nf], al[1], bh0, bh1);
            }
        }
        __syncthreads();
    }
    // write agg (fp32) to Ag
    #pragma unroll
    for (int m = 0; m < 2; m++)
        #pragma unroll
        for (int nf = 0; nf < 2; nf++) {
            int c0 = wid * 16 + nf * 8 + 2 * tig;
            int r = m * 16 + g;
            Ag[r * 132 + c0]       = acc[m][nf][0];
            Ag[r * 132 + c0 + 1]   = acc[m][nf][1];
            Ag[(r + 8) * 132 + c0]     = acc[m][nf][2];
            Ag[(r + 8) * 132 + c0 + 1] = acc[m][nf][3];
        }
    __syncthreads();

    // ---------------- stage 2: h = [agg | x] @ [pwaT ; pwoaT] ----------------
    float hacc[2][2][4];
    #pragma unroll
    for (int m = 0; m < 2; m++)
        #pragma unroll
        for (int n = 0; n < 2; n++)
            #pragma unroll
            for (int q = 0; q < 4; q++) hacc[m][n][q] = 0.f;

    for (int ch = 0; ch < 2; ch++) {
        if (ch == 0) {
            // A = agg split
            #pragma unroll
            for (int k = 0; k < 8; k++) {
                int e = tid + k * 256;
                int i = e >> 6, pp = e & 63;
                float2 v2 = *(const float2*)(Ag + i * 132 + 2 * pp);
                uint32_t hi, lo;
                split2(v2.x, v2.y, hi, lo);
                Ah[i * PPAD + pp] = hi;
                Al[i * PPAD + pp] = lo;
            }
        } else {
            // A = x rows it0..it0+31 (precomputed pairs)
            #pragma unroll
            for (int k = 0; k < 2; k++) {
                int e = tid + k * 256;      // 512 uint4
                int r = e >> 4, c4 = e & 15;
                ((uint4*)(Ah + r * PPAD))[c4] =
                    ((const uint4*)(d_xrh + ((size_t)b * NN + it0 + r) * 64))[c4];
                ((uint4*)(Al + r * PPAD))[c4] =
                    ((const uint4*)(d_xrl + ((size_t)b * NN + it0 + r) * 64))[c4];
            }
        }
        // B copy
        const uint32_t* srcH = ch ? d_poh : d_pah;
        const uint32_t* srcL = ch ? d_pol : d_pal;
        #pragma unroll
        for (int k = 0; k < 8; k++) {
            int e = tid + k * 256;
            int r = e >> 4, c4 = e & 15;
            ((uint4*)(Bh + r * PPAD))[c4] = ((const uint4*)(srcH + r * 64))[c4];
            ((uint4*)(Bl + r * PPAD))[c4] = ((const uint4*)(srcL + r * 64))[c4];
        }
        __syncthreads();
        #pragma unroll
        for (int k = 0; k < 8; k++) {
            uint32_t ah[2][4], al[2][4];
            #pragma unroll
            for (int m = 0; m < 2; m++) {
                const uint32_t* aph = Ah + (m * 16 + g) * PPAD + k * 8 + tig;
                const uint32_t* apl = Al + (m * 16 + g) * PPAD + k * 8 + tig;
                ah[m][0] = aph[0];            ah[m][1] = aph[8 * PPAD];
                ah[m][2] = aph[4];            ah[m][3] = aph[8 * PPAD + 4];
                al[m][0] = apl[0];            al[m][1] = apl[8 * PPAD];
                al[m][2] = apl[4];            al[m][3] = apl[8 * PPAD + 4];
            }
            #pragma unroll
            for (int nf = 0; nf < 2; nf++) {
                const uint32_t* bph = Bh + (wid * 16 + nf * 8 + g) * PPAD + k * 8 + tig;
                const uint32_t* bpl = Bl + (wid * 16 + nf * 8 + g) * PPAD + k * 8 + tig;
                uint32_t bh0 = bph[0], bh1 = bph[4];
                uint32_t bl0 = bpl[0], bl1 = bpl[4];
                mma_bf16(hacc[0][nf], ah[0], bh0, bh1);
                mma_bf16(hacc[1][nf], ah[1], bh0, bh1);
                mma_bf16(hacc[0][nf], ah[0], bl0, bl1);
                mma_bf16(hacc[1][nf], ah[1], bl0, bl1);
                mma_bf16(hacc[0][nf], al[0], bh0, bh1);
                mma_bf16(hacc[1][nf], al[1], bh0, bh1);
            }
        }
        __syncthreads();
    }

    // ---------------- epilogue: BN + selu + store + pool ----------------
    const float SELU_S = 1.0507009873554805f;
    const float SELU_A = 1.6732632423543772f;
    float prt[4] = {0.f, 0.f, 0.f, 0.f};
    #pragma unroll
    for (int m = 0; m < 2; m++) {
        #pragma unroll
        for (int nf = 0; nf < 2; nf++) {
            int c0 = wid * 16 + nf * 8 + 2 * tig;
            float sc0 = d_bnsc[c0], of0 = d_bnof[c0];
            float sc1 = d_bnsc[c0 + 1], of1 = d_bnof[c0 + 1];
            float pw0 = pool_w[c0], pw1 = pool_w[c0 + 1];
            #pragma unroll
            for (int half = 0; half < 2; half++) {
                int r = m * 16 + g + half * 8;
                float hv0 = hacc[m][nf][half * 2]     * sc0 + of0;
                float hv1 = hacc[m][nf][half * 2 + 1] * sc1 + of1;
                hv0 = (hv0 > 0.f) ? SELU_S * hv0 : SELU_S * SELU_A * (expf(hv0) - 1.f);
                hv1 = (hv1 > 0.f) ? SELU_S * hv1 : SELU_S * SELU_A * (expf(hv1) - 1.f);
                *(float2*)(d_h + ((size_t)b * NN + it0 + r) * DD + c0) =
                    make_float2(hv0, hv1);
                prt[m * 2 + half] += hv0 * pw0 + hv1 * pw1;
            }
        }
    }
    #pragma unroll
    for (int o = 1; o <= 2; o <<= 1) {
        prt[0] += __shfl_xor_sync(0xffffffffu, prt[0], o);
        prt[1] += __shfl_xor_sync(0xffffffffu, prt[1], o);
        prt[2] += __shfl_xor_sync(0xffffffffu, prt[2], o);
        prt[3] += __shfl_xor_sync(0xffffffffu, prt[3], o);
    }
    if (tig == 0) {
        PART[wid * 32 + g]      = prt[0];
        PART[wid * 32 + g + 8]  = prt[1];
        PART[wid * 32 + g + 16] = prt[2];
        PART[wid * 32 + g + 24] = prt[3];
    }
    __syncthreads();
    if (tid < 32) {
        float pacc = 0.f;
        #pragma unroll
        for (int w = 0; w < 8; w++) pacc += PART[w * 32 + tid];
        float sg = 1.f / (1.f + expf(-(pacc + pool_b[0])));
        d_scores[b * NN + it0 + tid] = sg;
    }
}

// ============================================================================
// Kernel 4: fused rank-select + gather. Block (q, b): ranks (redundant),
// gathers quarter of the 128 output rows.
// ============================================================================
__global__ void __launch_bounds__(256)
k4_topk(float* __restrict__ out) {
    const int b = blockIdx.y;
    const int q = blockIdx.x;
    const int tid = threadIdx.x;
    __shared__ float ss[NN];
    __shared__ int sp[KP];

    float s = d_scores[b * NN + tid];
    ss[tid] = s;
    __syncthreads();

    int r = 0;
    #pragma unroll 16
    for (int j = 0; j < NN; j++) {
        float sj = ss[j];
        r += (sj > s) || (sj == s && j < tid);
    }
    if (r < KP) sp[r] = tid;
    __syncthreads();

    // gather rows [q*32, q*32+32)
    #pragma unroll
    for (int k = 0; k < 4; k++) {
        int e = q * 1024 + k * 256 + tid;   // row*32 + c4
        int row = e >> 5, c4 = e & 31;
        int j = sp[row];
        float sv = ss[j];
        float4 v = ((const float4*)(d_h + ((size_t)b * NN + j) * DD))[c4];
        ((float4*)(out + ((size_t)b * KP + row) * DD))[c4] =
            make_float4(v.x * sv, v.y * sv, v.z * sv, v.w * sv);
    }
}

// ============================================================================
extern "C" void kernel_launch(void* const* d_in, const int* in_sizes, int n_in,
                              void* d_out, int out_size) {
    const float* x        = (const float*)d_in[0];
    const float* apw      = (const float*)d_in[1];
    const float* apb      = (const float*)d_in[2];
    const float* aweight  = (const float*)d_in[3];
    const float* pwa_w    = (const float*)d_in[4];
    const float* pwa_b    = (const float*)d_in[5];
    const float* pwoa_w   = (const float*)d_in[6];
    const float* pwoa_b   = (const float*)d_in[7];
    const float* bn_g     = (const float*)d_in[8];
    const float* bn_b     = (const float*)d_in[9];
    const float* bn_m     = (const float*)d_in[10];
    const float* bn_v     = (const float*)d_in[11];
    const float* pool_w   = (const float*)d_in[12];
    const float* pool_b   = (const float*)d_in[13];
    float* out = (float*)d_out;

    cudaFuncSetAttribute(k1_mma, cudaFuncAttributeMaxDynamicSharedMemorySize, SMEM1_REQ);
    cudaFuncSetAttribute(k3_tc,  cudaFuncAttributeMaxDynamicSharedMemorySize, SMEM3);

    k0_prep<<<2145, 256>>>(apw, x, pwa_w, pwoa_w, pwa_b, pwoa_b,
                           bn_g, bn_b, bn_m, bn_v);
    k1_mma<<<dim3(NN / 2, BB), 256, SMEM1_REQ>>>(x, apb, aweight);
    k2r_rowstat<<<dim3(NN / 8, BB), 256>>>();
    k3_tc<<<dim3(NN / 32, BB), 256, SMEM3>>>(pool_w, pool_b);
    k4_topk<<<dim3(4, BB), 256>>>(out);
}

// round 13
// speedup vs baseline: 4.9802x; 1.1582x over previous
#include <cuda_runtime.h>
#include <math.h>
#include <stdint.h>

#define BB 16
#define NN 256
#define DD 128
#define KP 128
#define LOG2E 1.4426950408889634f

// -------- scratch (device globals; no allocation allowed) --------
__device__ float    d_logits[(size_t)BB * NN * NN];   // 4 MB (raw logits)
__device__ float    d_h[(size_t)BB * NN * DD];        // 2 MB
__device__ float    d_scores[BB * NN];
__device__ float    d_rowM[BB * NN];
__device__ float    d_rowIS[BB * NN];
__device__ uint32_t d_wbh[DD * 64];                   // W^T hi bf16x2 pairs [c][p]
__device__ uint32_t d_wbl[DD * 64];
__device__ uint32_t d_pah[DD * 64], d_pal[DD * 64];   // pwa_w^T pairs [c][p over d]
__device__ uint32_t d_poh[DD * 64], d_pol[DD * 64];   // pwoa_w^T pairs
__device__ uint32_t d_xrh[BB * NN * 64];              // x row-major pairs [b][j][p over d]
__device__ uint32_t d_xrl[BB * NN * 64];
__device__ uint32_t d_xth[BB * DD * 128];             // x^T pairs [b][d][p over j]
__device__ uint32_t d_xtl[BB * DD * 128];
__device__ float    d_bnsc[DD], d_bnof[DD];           // folded BN scale/offset

__device__ __forceinline__ float tanh_approx(float x) {
    float y; asm("tanh.approx.f32 %0, %1;" : "=f"(y) : "f"(x)); return y;
}
__device__ __forceinline__ uint32_t pack_bf16x2(float e0, float e1) {
    uint32_t u;
    asm("cvt.rn.bf16x2.f32 %0, %1, %2;" : "=r"(u) : "f"(e1), "f"(e0));
    return u;
}
__device__ __forceinline__ void split2(float a0, float a1, uint32_t& hi, uint32_t& lo) {
    hi = pack_bf16x2(a0, a1);
    float r0 = a0 - __uint_as_float(hi << 16);
    float r1 = a1 - __uint_as_float(hi & 0xffff0000u);
    lo = pack_bf16x2(r0, r1);
}
__device__ __forceinline__ void mma_bf16(float* c, const uint32_t* a,
                                         uint32_t b0, uint32_t b1) {
    asm volatile(
        "mma.sync.aligned.m16n8k16.row.col.f32.bf16.bf16.f32 "
        "{%0,%1,%2,%3}, {%4,%5,%6,%7}, {%8,%9}, {%0,%1,%2,%3};"
        : "+f"(c[0]), "+f"(c[1]), "+f"(c[2]), "+f"(c[3])
        : "r"(a[0]), "r"(a[1]), "r"(a[2]), "r"(a[3]), "r"(b0), "r"(b1));
}

// ============================================================================
// Kernel 0 (exact R8 version — known good): preprocessing splits.
//  blk [0,32):    W^T split (k1)
//  blk [32,96):   pwa_w^T / pwoa_w^T splits
//  blk [96,1120): x row-major pair split
//  blk [1120,2144): x^T pair split (strided reads; slow but verified)
//  blk 2144:      BN fold
// ============================================================================
__global__ void k0_prep(const float* __restrict__ W, const float* __restrict__ x,
                        const float* __restrict__ pwa_w, const float* __restrict__ pwoa_w,
                        const float* __restrict__ pwa_b, const float* __restrict__ pwoa_b,
                        const float* __restrict__ bn_g, const float* __restrict__ bn_b,
                        const float* __restrict__ bn_m, const float* __restrict__ bn_v) {
    int blk = blockIdx.x, tid = threadIdx.x;
    if (blk < 32) {
        int idx = blk * 256 + tid;
        int c = idx >> 6, p = idx & 63;
        uint32_t hi, lo;
        split2(W[(size_t)(2 * p) * DD + c], W[(size_t)(2 * p + 1) * DD + c], hi, lo);
        d_wbh[idx] = hi; d_wbl[idx] = lo;
    } else if (blk < 96) {
        int idx = (blk - 32) * 256 + tid;
        int mat = idx >> 13;
        int r = idx & 8191;
        int c = r >> 6, p = r & 63;
        const float* src = mat ? pwoa_w : pwa_w;
        uint32_t hi, lo;
        split2(src[(size_t)(2 * p) * DD + c], src[(size_t)(2 * p + 1) * DD + c], hi, lo);
        if (mat) { d_poh[r] = hi; d_pol[r] = lo; }
        else     { d_pah[r] = hi; d_pal[r] = lo; }
    } else if (blk < 1120) {
        int idx = (blk - 96) * 256 + tid;   // b*16384 + j*64 + p
        int p = idx & 63;
        const float* xp = x + (size_t)(idx >> 6) * DD;
        uint32_t hi, lo;
        split2(xp[2 * p], xp[2 * p + 1], hi, lo);
        d_xrh[idx] = hi; d_xrl[idx] = lo;
    } else if (blk < 2144) {
        int idx = (blk - 1120) * 256 + tid; // 0..262143 = b*16384 + d*128 + p
        int bb = idx >> 14;
        int d = (idx >> 7) & 127;
        int p = idx & 127;
        const float* xp = x + ((size_t)bb * NN + 2 * p) * DD + d;
        uint32_t hi, lo;
        split2(xp[0], xp[DD], hi, lo);
        d_xth[idx] = hi; d_xtl[idx] = lo;
    } else {
        if (tid < DD) {
            float sc = bn_g[tid] * rsqrtf(bn_v[tid] + 1e-5f);
            d_bnsc[tid] = sc;
            d_bnof[tid] = (pwa_b[tid] + pwoa_b[tid] - bn_m[tid]) * sc + bn_b[tid];
        }
    }
}

#define PPAD 68
// k1 smem (M=32): Ah/Al [32][PPAD], Bh/Bl [128][PPAD], XI[2][128], BSs, VS, PART[256]
#define SMEM1_REQ ((2 * 32 * PPAD + 2 * 128 * PPAD + 256 + 128 + 128 + 256) * 4)

// ============================================================================
// Kernel 1: symmetric-pair, M=32 j-tiles (9 tiles/pair = 288 rows vs 320, -10%).
// Block (p,b) owns i1=p, i2=255-p. Warp w covers cols [16w,16w+16), all 32 rows.
// ============================================================================
__global__ void __launch_bounds__(256, 2)
k1_mma(const float* __restrict__ x, const float* __restrict__ bias,
       const float* __restrict__ v) {
    extern __shared__ uint32_t sm[];
    uint32_t* Ah = sm;                        // [32][PPAD]
    uint32_t* Al = Ah + 32 * PPAD;
    uint32_t* Bh = Al + 32 * PPAD;            // [128][PPAD]
    uint32_t* Bl = Bh + 128 * PPAD;
    float* XI   = (float*)(Bl + 128 * PPAD);  // [2][128]
    float* BSs  = XI + 256;
    float* VS   = BSs + 128;
    float* PART = VS + 128;                   // [8][32]

    const int p = blockIdx.x, b = blockIdx.y;
    const int i1 = p, i2 = NN - 1 - p;
    const int tid = threadIdx.x;
    const int wid = tid >> 5, lid = tid & 31;
    const int g = lid >> 2, tig = lid & 3;
    const float* xb = x + (size_t)b * NN * DD;

    if (tid < 128) {
        XI[tid]       = xb[(size_t)i1 * DD + tid];
        XI[128 + tid] = xb[(size_t)i2 * DD + tid];
        BSs[tid] = bias[tid];
        VS[tid]  = v[tid];
    }
    #pragma unroll
    for (int k = 0; k < 8; k++) {
        int e = tid + k * 256;
        int r = e >> 4, c4 = e & 15;
        ((uint4*)(Bh + r * PPAD))[c4] = ((const uint4*)d_wbh)[e];
        ((uint4*)(Bl + r * PPAD))[c4] = ((const uint4*)d_wbl)[e];
    }
    __syncthreads();

    for (int xi = 0; xi < 2; xi++) {
        const int ii = xi ? i2 : i1;
        const float* xisel = XI + xi * 128;
        for (int j0 = 0; j0 < NN; j0 += 32) {
            if (j0 + 31 < ii) continue;
            const int jmin = (ii > j0) ? (ii - j0) : 0;

            // A build: 32 rows; thread = (r = tid>>3, 16-d group)
            {
                int r  = tid >> 3;
                int dg = (tid & 7) * 16;
                const float4* xr  = (const float4*)(xb + (size_t)(j0 + r) * DD + dg);
                const float4* xi4 = (const float4*)(xisel + dg);
                uint32_t* ahr = Ah + r * PPAD + (dg >> 1);
                uint32_t* alr = Al + r * PPAD + (dg >> 1);
                #pragma unroll
                for (int q = 0; q < 4; q++) {
                    float4 xv = xr[q], iv = xi4[q];
                    uint32_t h0, l0, h1, l1;
                    split2(xv.x * iv.x, xv.y * iv.y, h0, l0);
                    split2(xv.z * iv.z, xv.w * iv.w, h1, l1);
                    ahr[q * 2]     = h0;
                    ahr[q * 2 + 1] = h1;
                    alr[q * 2]     = l0;
                    alr[q * 2 + 1] = l1;
                }
            }
            __syncthreads();

            float acc[2][2][4];
            #pragma unroll
            for (int m = 0; m < 2; m++)
                #pragma unroll
                for (int n = 0; n < 2; n++)
                    #pragma unroll
                    for (int q = 0; q < 4; q++) acc[m][n][q] = 0.f;

            #pragma unroll
            for (int k = 0; k < 8; k++) {
                uint32_t ah[2][4], al[2][4];
                #pragma unroll
                for (int m = 0; m < 2; m++) {
                    const uint32_t* aph = Ah + (m * 16 + g) * PPAD + k * 8 + tig;
                    const uint32_t* apl = Al + (m * 16 + g) * PPAD + k * 8 + tig;
                    ah[m][0] = aph[0];            ah[m][1] = aph[8 * PPAD];
                    ah[m][2] = aph[4];            ah[m][3] = aph[8 * PPAD + 4];
                    al[m][0] = apl[0];            al[m][1] = apl[8 * PPAD];
                    al[m][2] = apl[4];            al[m][3] = apl[8 * PPAD + 4];
                }
                #pragma unroll
                for (int nf = 0; nf < 2; nf++) {
                    const uint32_t* bph = Bh + (wid * 16 + nf * 8 + g) * PPAD + k * 8 + tig;
                    const uint32_t* bpl = Bl + (wid * 16 + nf * 8 + g) * PPAD + k * 8 + tig;
                    uint32_t bh0 = bph[0], bh1 = bph[4];
                    uint32_t bl0 = bpl[0], bl1 = bpl[4];
                    mma_bf16(acc[0][nf], ah[0], bh0, bh1);
                    mma_bf16(acc[1][nf], ah[1], bh0, bh1);
                    mma_bf16(acc[0][nf], ah[0], bl0, bl1);
                    mma_bf16(acc[1][nf], ah[1], bl0, bl1);
                    mma_bf16(acc[0][nf], al[0], bh0, bh1);
                    mma_bf16(acc[1][nf], al[1], bh0, bh1);
                }
            }

            // epilogue: tanh + v-dot over this warp's 16 cols
            float prt[4] = {0.f, 0.f, 0.f, 0.f};
            #pragma unroll
            for (int m = 0; m < 2; m++) {
                #pragma unroll
                for (int nf = 0; nf < 2; nf++) {
                    int c0 = wid * 16 + nf * 8 + 2 * tig;
                    float v0 = VS[c0], v1 = VS[c0 + 1];
                    float b0 = BSs[c0], b1 = BSs[c0 + 1];
                    prt[2 * m + 0] += v0 * tanh_approx(acc[m][nf][0] + b0)
                                    + v1 * tanh_approx(acc[m][nf][1] + b1);
                    prt[2 * m + 1] += v0 * tanh_approx(acc[m][nf][2] + b0)
                                    + v1 * tanh_approx(acc[m][nf][3] + b1);
                }
            }
            #pragma unroll
            for (int o = 1; o <= 2; o <<= 1) {
                prt[0] += __shfl_xor_sync(0xffffffffu, prt[0], o);
                prt[1] += __shfl_xor_sync(0xffffffffu, prt[1], o);
                prt[2] += __shfl_xor_sync(0xffffffffu, prt[2], o);
                prt[3] += __shfl_xor_sync(0xffffffffu, prt[3], o);
            }
            if (tig == 0) {
                PART[wid * 32 + g]      = prt[0];
                PART[wid * 32 + g + 8]  = prt[1];
                PART[wid * 32 + g + 16] = prt[2];
                PART[wid * 32 + g + 24] = prt[3];
            }
            __syncthreads();
            if (tid < 32 && tid >= jmin) {
                float lg = 0.f;
                #pragma unroll
                for (int w = 0; w < 8; w++) lg += PART[w * 32 + tid];
                int j = j0 + tid;
                d_logits[((size_t)b * NN + ii) * NN + j] = lg;
                d_logits[((size_t)b * NN + j) * NN + ii] = lg;
            }
            __syncthreads();
        }
    }
}

// ============================================================================
// Kernel 2r: per-row max and 1/sum(exp).
// ============================================================================
__global__ void __launch_bounds__(256)
k2r_rowstat() {
    const int b = blockIdx.y;
    const int row = blockIdx.x * 8 + (threadIdx.x >> 5);
    const int lane = threadIdx.x & 31;
    const float* rp = d_logits + ((size_t)b * NN + row) * NN;

    float4 a0 = ((const float4*)rp)[lane * 2];
    float4 a1 = ((const float4*)rp)[lane * 2 + 1];
    float m = fmaxf(fmaxf(fmaxf(a0.x, a0.y), fmaxf(a0.z, a0.w)),
                    fmaxf(fmaxf(a1.x, a1.y), fmaxf(a1.z, a1.w)));
    #pragma unroll
    for (int o = 16; o > 0; o >>= 1) m = fmaxf(m, __shfl_xor_sync(0xffffffffu, m, o));

    float s = exp2f((a0.x - m) * LOG2E) + exp2f((a0.y - m) * LOG2E)
            + exp2f((a0.z - m) * LOG2E) + exp2f((a0.w - m) * LOG2E)
            + exp2f((a1.x - m) * LOG2E) + exp2f((a1.y - m) * LOG2E)
            + exp2f((a1.z - m) * LOG2E) + exp2f((a1.w - m) * LOG2E);
    #pragma unroll
    for (int o = 16; o > 0; o >>= 1) s += __shfl_xor_sync(0xffffffffu, s, o);

    if (lane == 0) {
        d_rowM[b * NN + row]  = m;
        d_rowIS[b * NN + row] = 1.f / s;
    }
}

// ============================================================================
// Kernel 3 (tensor-core, exact R8 version): per CTA 32 i-rows.
// stage1: agg = att @ x; stage2: h = [agg | x] @ [pwa^T ; pwoa^T]; BN/selu/pool.
// ============================================================================
#define SMEM3 ((2 * 32 * PPAD + 2 * 128 * PPAD) * 4 + (32 * 132 + 256) * 4)

__global__ void __launch_bounds__(256, 2)
k3_tc(const float* __restrict__ pool_w, const float* __restrict__ pool_b) {
    extern __shared__ uint32_t sm3u[];
    uint32_t* Ah = sm3u;                       // [32][PPAD]
    uint32_t* Al = Ah + 32 * PPAD;
    uint32_t* Bh = Al + 32 * PPAD;             // [128][PPAD]
    uint32_t* Bl = Bh + 128 * PPAD;
    float* Ag   = (float*)(Bl + 128 * PPAD);   // [32][132]; doubles as Et
    float* PART = Ag + 32 * 132;               // [256]

    const int b = blockIdx.y;
    const int it0 = blockIdx.x * 32;
    const int tid = threadIdx.x;
    const int wid = tid >> 5, lid = tid & 31;
    const int g = lid >> 2, tig = lid & 3;

    float acc[2][2][4];
    #pragma unroll
    for (int m = 0; m < 2; m++)
        #pragma unroll
        for (int n = 0; n < 2; n++)
            #pragma unroll
            for (int q = 0; q < 4; q++) acc[m][n][q] = 0.f;

    // ---------------- stage 1: agg = att @ x ----------------
    for (int ch = 0; ch < 2; ch++) {
        const int j0 = ch * 128;
        #pragma unroll
        for (int k = 0; k < 4; k++) {
            int e = tid + k * 256;
            int jr = e >> 3, ic4 = e & 7;
            int row = j0 + jr;
            float M  = d_rowM[b * NN + row];
            float IS = d_rowIS[b * NN + row];
            float4 rv = ((const float4*)(d_logits + ((size_t)b * NN + row) * NN + it0))[ic4];
            Ag[(ic4 * 4 + 0) * 132 + jr] = exp2f((rv.x - M) * LOG2E) * IS;
            Ag[(ic4 * 4 + 1) * 132 + jr] = exp2f((rv.y - M) * LOG2E) * IS;
            Ag[(ic4 * 4 + 2) * 132 + jr] = exp2f((rv.z - M) * LOG2E) * IS;
            Ag[(ic4 * 4 + 3) * 132 + jr] = exp2f((rv.w - M) * LOG2E) * IS;
        }
        __syncthreads();
        #pragma unroll
        for (int k = 0; k < 8; k++) {
            int e = tid + k * 256;
            int i = e >> 6, pp = e & 63;
            float2 v2 = *(const float2*)(Ag + i * 132 + 2 * pp);
            uint32_t hi, lo;
            split2(v2.x, v2.y, hi, lo);
            Ah[i * PPAD + pp] = hi;
            Al[i * PPAD + pp] = lo;
        }
        #pragma unroll
        for (int k = 0; k < 8; k++) {
            int e = tid + k * 256;
            int r = e >> 4, c4 = e & 15;
            ((uint4*)(Bh + r * PPAD))[c4] =
                ((const uint4*)(d_xth + ((size_t)b * DD + r) * 128 + ch * 64))[c4];
            ((uint4*)(Bl + r * PPAD))[c4] =
                ((const uint4*)(d_xtl + ((size_t)b * DD + r) * 128 + ch * 64))[c4];
        }
        __syncthreads();
        #pragma unroll
        for (int k = 0; k < 8; k++) {
            uint32_t ah[2][4], al[2][4];
            #pragma unroll
            for (int m = 0; m < 2; m++) {
                const uint32_t* aph = Ah + (m * 16 + g) * PPAD + k * 8 + tig;
                const uint32_t* apl = Al + (m * 16 + g) * PPAD + k * 8 + tig;
                ah[m][0] = aph[0];            ah[m][1] = aph[8 * PPAD];
                ah[m][2] = aph[4];            ah[m][3] = aph[8 * PPAD + 4];
                al[m][0] = apl[0];            al[m][1] = apl[8 * PPAD];
                al[m][2] = apl[4];            al[m][3] = apl[8 * PPAD + 4];
            }
            #pragma unroll
            for (int nf = 0; nf < 2; nf++) {
                const uint32_t* bph = Bh + (wid * 16 + nf * 8 + g) * PPAD + k * 8 + tig;
                const uint32_t* bpl = Bl + (wid * 16 + nf * 8 + g) * PPAD + k * 8 + tig;
                uint32_t bh0 = bph[0], bh1 = bph[4];
                uint32_t bl0 = bpl[0], bl1 = bpl[4];
                mma_bf16(acc[0][nf], ah[0], bh0, bh1);
                mma_bf16(acc[1][nf], ah[1], bh0, bh1);
                mma_bf16(acc[0][nf], ah[0], bl0, bl1);
                mma_bf16(acc[1][nf], ah[1], bl0, bl1);
                mma_bf16(acc[0][nf], al[0], bh0, bh1);
                mma_bf16(acc[1][nf], al[1], bh0, bh1);
            }
        }
        __syncthreads();
    }
    #pragma unroll
    for (int m = 0; m < 2; m++)
        #pragma unroll
        for (int nf = 0; nf < 2; nf++) {
            int c0 = wid * 16 + nf * 8 + 2 * tig;
            int r = m * 16 + g;
            Ag[r * 132 + c0]       = acc[m][nf][0];
            Ag[r * 132 + c0 + 1]   = acc[m][nf][1];
            Ag[(r + 8) * 132 + c0]     = acc[m][nf][2];
            Ag[(r + 8) * 132 + c0 + 1] = acc[m][nf][3];
        }
    __syncthreads();

    // ---------------- stage 2: h = [agg | x] @ [pwaT ; pwoaT] ----------------
    float hacc[2][2][4];
    #pragma unroll
    for (int m = 0; m < 2; m++)
        #pragma unroll
        for (int n = 0; n < 2; n++)
            #pragma unroll
            for (int q = 0; q < 4; q++) hacc[m][n][q] = 0.f;

    for (int ch = 0; ch < 2; ch++) {
        if (ch == 0) {
            #pragma unroll
            for (int k = 0; k < 8; k++) {
                int e = tid + k * 256;
                int i = e >> 6, pp = e & 63;
                float2 v2 = *(const float2*)(Ag + i * 132 + 2 * pp);
                uint32_t hi, lo;
                split2(v2.x, v2.y, hi, lo);
                Ah[i * PPAD + pp] = hi;
                Al[i * PPAD + pp] = lo;
            }
        } else {
            #pragma unroll
            for (int k = 0; k < 2; k++) {
                int e = tid + k * 256;
                int r = e >> 4, c4 = e & 15;
                ((uint4*)(Ah + r * PPAD))[c4] =
                    ((const uint4*)(d_xrh + ((size_t)b * NN + it0 + r) * 64))[c4];
                ((uint4*)(Al + r * PPAD))[c4] =
                    ((const uint4*)(d_xrl + ((size_t)b * NN + it0 + r) * 64))[c4];
            }
        }
        const uint32_t* srcH = ch ? d_poh : d_pah;
        const uint32_t* srcL = ch ? d_pol : d_pal;
        #pragma unroll
        for (int k = 0; k < 8; k++) {
            int e = tid + k * 256;
            int r = e >> 4, c4 = e & 15;
            ((uint4*)(Bh + r * PPAD))[c4] = ((const uint4*)(srcH + r * 64))[c4];
            ((uint4*)(Bl + r * PPAD))[c4] = ((const uint4*)(srcL + r * 64))[c4];
        }
        __syncthreads();
        #pragma unroll
        for (int k = 0; k < 8; k++) {
            uint32_t ah[2][4], al[2][4];
            #pragma unroll
            for (int m = 0; m < 2; m++) {
                const uint32_t* aph = Ah + (m * 16 + g) * PPAD + k * 8 + tig;
                const uint32_t* apl = Al + (m * 16 + g) * PPAD + k * 8 + tig;
                ah[m][0] = aph[0];            ah[m][1] = aph[8 * PPAD];
                ah[m][2] = aph[4];            ah[m][3] = aph[8 * PPAD + 4];
                al[m][0] = apl[0];            al[m][1] = apl[8 * PPAD];
                al[m][2] = apl[4];            al[m][3] = apl[8 * PPAD + 4];
            }
            #pragma unroll
            for (int nf = 0; nf < 2; nf++) {
                const uint32_t* bph = Bh + (wid * 16 + nf * 8 + g) * PPAD + k * 8 + tig;
                const uint32_t* bpl = Bl + (wid * 16 + nf * 8 + g) * PPAD + k * 8 + tig;
                uint32_t bh0 = bph[0], bh1 = bph[4];
                uint32_t bl0 = bpl[0], bl1 = bpl[4];
                mma_bf16(hacc[0][nf], ah[0], bh0, bh1);
                mma_bf16(hacc[1][nf], ah[1], bh0, bh1);
                mma_bf16(hacc[0][nf], ah[0], bl0, bl1);
                mma_bf16(hacc[1][nf], ah[1], bl0, bl1);
                mma_bf16(hacc[0][nf], al[0], bh0, bh1);
                mma_bf16(hacc[1][nf], al[1], bh0, bh1);
            }
        }
        __syncthreads();
    }

    // ---------------- epilogue: BN + selu + store + pool ----------------
    const float SELU_S = 1.0507009873554805f;
    const float SELU_A = 1.6732632423543772f;
    float prt[4] = {0.f, 0.f, 0.f, 0.f};
    #pragma unroll
    for (int m = 0; m < 2; m++) {
        #pragma unroll
        for (int nf = 0; nf < 2; nf++) {
            int c0 = wid * 16 + nf * 8 + 2 * tig;
            float sc0 = d_bnsc[c0], of0 = d_bnof[c0];
            float sc1 = d_bnsc[c0 + 1], of1 = d_bnof[c0 + 1];
            float pw0 = pool_w[c0], pw1 = pool_w[c0 + 1];
            #pragma unroll
            for (int half = 0; half < 2; half++) {
                int r = m * 16 + g + half * 8;
                float hv0 = hacc[m][nf][half * 2]     * sc0 + of0;
                float hv1 = hacc[m][nf][half * 2 + 1] * sc1 + of1;
                hv0 = (hv0 > 0.f) ? SELU_S * hv0 : SELU_S * SELU_A * (expf(hv0) - 1.f);
                hv1 = (hv1 > 0.f) ? SELU_S * hv1 : SELU_S * SELU_A * (expf(hv1) - 1.f);
                *(float2*)(d_h + ((size_t)b * NN + it0 + r) * DD + c0) =
                    make_float2(hv0, hv1);
                prt[m * 2 + half] += hv0 * pw0 + hv1 * pw1;
            }
        }
    }
    #pragma unroll
    for (int o = 1; o <= 2; o <<= 1) {
        prt[0] += __shfl_xor_sync(0xffffffffu, prt[0], o);
        prt[1] += __shfl_xor_sync(0xffffffffu, prt[1], o);
        prt[2] += __shfl_xor_sync(0xffffffffu, prt[2], o);
        prt[3] += __shfl_xor_sync(0xffffffffu, prt[3], o);
    }
    if (tig == 0) {
        PART[wid * 32 + g]      = prt[0];
        PART[wid * 32 + g + 8]  = prt[1];
        PART[wid * 32 + g + 16] = prt[2];
        PART[wid * 32 + g + 24] = prt[3];
    }
    __syncthreads();
    if (tid < 32) {
        float pacc = 0.f;
        #pragma unroll
        for (int w = 0; w < 8; w++) pacc += PART[w * 32 + tid];
        float sg = 1.f / (1.f + expf(-(pacc + pool_b[0])));
        d_scores[b * NN + it0 + tid] = sg;
    }
}

// ============================================================================
// Kernel 4: fused rank-select + gather.
// ============================================================================
__global__ void __launch_bounds__(256)
k4_topk(float* __restrict__ out) {
    const int b = blockIdx.y;
    const int q = blockIdx.x;
    const int tid = threadIdx.x;
    __shared__ float ss[NN];
    __shared__ int sp[KP];

    float s = d_scores[b * NN + tid];
    ss[tid] = s;
    __syncthreads();

    int r = 0;
    #pragma unroll 16
    for (int j = 0; j < NN; j++) {
        float sj = ss[j];
        r += (sj > s) || (sj == s && j < tid);
    }
    if (r < KP) sp[r] = tid;
    __syncthreads();

    #pragma unroll
    for (int k = 0; k < 4; k++) {
        int e = q * 1024 + k * 256 + tid;
        int row = e >> 5, c4 = e & 31;
        int j = sp[row];
        float sv = ss[j];
        float4 v = ((const float4*)(d_h + ((size_t)b * NN + j) * DD))[c4];
        ((float4*)(out + ((size_t)b * KP + row) * DD))[c4] =
            make_float4(v.x * sv, v.y * sv, v.z * sv, v.w * sv);
    }
}

// ============================================================================
extern "C" void kernel_launch(void* const* d_in, const int* in_sizes, int n_in,
                              void* d_out, int out_size) {
    const float* x        = (const float*)d_in[0];
    const float* apw      = (const float*)d_in[1];
    const float* apb      = (const float*)d_in[2];
    const float* aweight  = (const float*)d_in[3];
    const float* pwa_w    = (const float*)d_in[4];
    const float* pwa_b    = (const float*)d_in[5];
    const float* pwoa_w   = (const float*)d_in[6];
    const float* pwoa_b   = (const float*)d_in[7];
    const float* bn_g     = (const float*)d_in[8];
    const float* bn_b     = (const float*)d_in[9];
    const float* bn_m     = (const float*)d_in[10];
    const float* bn_v     = (const float*)d_in[11];
    const float* pool_w   = (const float*)d_in[12];
    const float* pool_b   = (const float*)d_in[13];
    float* out = (float*)d_out;

    cudaFuncSetAttribute(k1_mma, cudaFuncAttributeMaxDynamicSharedMemorySize, SMEM1_REQ);
    cudaFuncSetAttribute(k3_tc,  cudaFuncAttributeMaxDynamicSharedMemorySize, SMEM3);

    k0_prep<<<2145, 256>>>(apw, x, pwa_w, pwoa_w, pwa_b, pwoa_b,
                           bn_g, bn_b, bn_m, bn_v);
    k1_mma<<<dim3(NN / 2, BB), 256, SMEM1_REQ>>>(x, apb, aweight);
    k2r_rowstat<<<dim3(NN / 8, BB), 256>>>();
    k3_tc<<<dim3(NN / 32, BB), 256, SMEM3>>>(pool_w, pool_b);
    k4_topk<<<dim3(4, BB), 256>>>(out);
}

// round 16
// speedup vs baseline: 4.9898x; 1.0019x over previous
#include <cuda_runtime.h>
#include <math.h>
#include <stdint.h>

#define BB 16
#define NN 256
#define DD 128
#define KP 128
#define LOG2E 1.4426950408889634f

// -------- scratch (device globals; no allocation allowed) --------
__device__ float    d_logits[(size_t)BB * NN * NN];   // 4 MB (raw logits)
__device__ float    d_h[(size_t)BB * NN * DD];        // 2 MB
__device__ float    d_scores[BB * NN];
__device__ float    d_rowM[BB * NN];
__device__ float    d_rowIS[BB * NN];
__device__ uint32_t d_wbh[DD * 64];                   // W^T hi bf16x2 pairs [c][p]
__device__ uint32_t d_wbl[DD * 64];
__device__ uint32_t d_pah[DD * 64], d_pal[DD * 64];   // pwa_w^T pairs [c][p over d]
__device__ uint32_t d_poh[DD * 64], d_pol[DD * 64];   // pwoa_w^T pairs
__device__ uint32_t d_xrh[BB * NN * 64];              // x row-major pairs [b][j][p over d]
__device__ uint32_t d_xrl[BB * NN * 64];
__device__ uint32_t d_xth[BB * DD * 128];             // x^T pairs [b][d][p over j]
__device__ uint32_t d_xtl[BB * DD * 128];
__device__ float    d_bnsc[DD], d_bnof[DD];           // folded BN scale/offset

__device__ __forceinline__ float tanh_approx(float x) {
    float y; asm("tanh.approx.f32 %0, %1;" : "=f"(y) : "f"(x)); return y;
}
__device__ __forceinline__ uint32_t pack_bf16x2(float e0, float e1) {
    uint32_t u;
    asm("cvt.rn.bf16x2.f32 %0, %1, %2;" : "=r"(u) : "f"(e1), "f"(e0));
    return u;
}
__device__ __forceinline__ void split2(float a0, float a1, uint32_t& hi, uint32_t& lo) {
    hi = pack_bf16x2(a0, a1);
    float r0 = a0 - __uint_as_float(hi << 16);
    float r1 = a1 - __uint_as_float(hi & 0xffff0000u);
    lo = pack_bf16x2(r0, r1);
}
__device__ __forceinline__ void mma_bf16(float* c, const uint32_t* a,
                                         uint32_t b0, uint32_t b1) {
    asm volatile(
        "mma.sync.aligned.m16n8k16.row.col.f32.bf16.bf16.f32 "
        "{%0,%1,%2,%3}, {%4,%5,%6,%7}, {%8,%9}, {%0,%1,%2,%3};"
        : "+f"(c[0]), "+f"(c[1]), "+f"(c[2]), "+f"(c[3])
        : "r"(a[0]), "r"(a[1]), "r"(a[2]), "r"(a[3]), "r"(b0), "r"(b1));
}

// ============================================================================
// Kernel 0: preprocessing splits.
//  blk [0,32):      W^T split (k1)
//  blk [32,96):     pwa_w^T / pwoa_w^T splits
//  blk [96,1120):   x row-major pair split
//  blk [1120,1184): x^T pair split via smem transpose
//                   CORRECT grid: 64 blocks, bb=q>>2 (16 batches) x rc=q&3
//                   (4 chunks of 64 rows = 256 rows; p = rc*32+pl in [0,128))
//  blk 1184:        BN fold
// ============================================================================
__global__ void k0_prep(const float* __restrict__ W, const float* __restrict__ x,
                        const float* __restrict__ pwa_w, const float* __restrict__ pwoa_w,
                        const float* __restrict__ pwa_b, const float* __restrict__ pwoa_b,
                        const float* __restrict__ bn_g, const float* __restrict__ bn_b,
                        const float* __restrict__ bn_m, const float* __restrict__ bn_v) {
    int blk = blockIdx.x, tid = threadIdx.x;
    if (blk < 32) {
        int idx = blk * 256 + tid;
        int c = idx >> 6, p = idx & 63;
        uint32_t hi, lo;
        split2(W[(size_t)(2 * p) * DD + c], W[(size_t)(2 * p + 1) * DD + c], hi, lo);
        d_wbh[idx] = hi; d_wbl[idx] = lo;
    } else if (blk < 96) {
        int idx = (blk - 32) * 256 + tid;
        int mat = idx >> 13;
        int r = idx & 8191;
        int c = r >> 6, p = r & 63;
        const float* src = mat ? pwoa_w : pwa_w;
        uint32_t hi, lo;
        split2(src[(size_t)(2 * p) * DD + c], src[(size_t)(2 * p + 1) * DD + c], hi, lo);
        if (mat) { d_poh[r] = hi; d_pol[r] = lo; }
        else     { d_pah[r] = hi; d_pal[r] = lo; }
    } else if (blk < 1120) {
        int idx = (blk - 96) * 256 + tid;   // b*16384 + j*64 + p
        int p = idx & 63;
        const float* xp = x + (size_t)(idx >> 6) * DD;
        uint32_t hi, lo;
        split2(xp[2 * p], xp[2 * p + 1], hi, lo);
        d_xrh[idx] = hi; d_xrl[idx] = lo;
    } else if (blk < 1184) {
        // coalesced smem transpose: batch bb, rows [rc*64, rc*64+64)
        __shared__ float ts[64 * 129];
        int q = blk - 1120;                 // 0..63
        int bb = q >> 2;                    // 0..15
        int rc = q & 3;                     // 0..3  (4 x 64 rows = 256)
        const float* xs = x + ((size_t)bb * NN + rc * 64) * DD;
        #pragma unroll
        for (int k = 0; k < 8; k++) {
            int e = k * 256 + tid;          // 2048 float4 = 64 rows x 32 c4
            int r = e >> 5, c4 = e & 31;
            float4 v = ((const float4*)(xs + (size_t)r * DD))[c4];
            float* dstp = ts + r * 129 + c4 * 4;
            dstp[0] = v.x; dstp[1] = v.y; dstp[2] = v.z; dstp[3] = v.w;
        }
        __syncthreads();
        #pragma unroll
        for (int k = 0; k < 16; k++) {
            int e = k * 256 + tid;          // 4096: d*32 + pl
            int d = e >> 5, pl = e & 31;    // d in 0..127, pl in 0..31
            float y0 = ts[(2 * pl) * 129 + d];
            float y1 = ts[(2 * pl + 1) * 129 + d];
            uint32_t hi, lo;
            split2(y0, y1, hi, lo);
            size_t o = ((size_t)bb * DD + d) * 128 + rc * 32 + pl;  // p in [0,128)
            d_xth[o] = hi; d_xtl[o] = lo;
        }
    } else {
        if (tid < DD) {
            float sc = bn_g[tid] * rsqrtf(bn_v[tid] + 1e-5f);
            d_bnsc[tid] = sc;
            d_bnof[tid] = (pwa_b[tid] + pwoa_b[tid] - bn_m[tid]) * sc + bn_b[tid];
        }
    }
}

#define PPAD 68
// k1 smem (M=32): Ah/Al [32][PPAD], Bh/Bl [128][PPAD], XI[2][128], BSs, VS, PART[256]
#define SMEM1_REQ ((2 * 32 * PPAD + 2 * 128 * PPAD + 256 + 128 + 128 + 256) * 4)

// ============================================================================
// Kernel 1 (verified R13): symmetric-pair, M=32 j-tiles, bf16x3 mma.
// Block (p,b) owns i1=p, i2=255-p. Warp w covers cols [16w,16w+16), all 32 rows.
// ============================================================================
__global__ void __launch_bounds__(256, 2)
k1_mma(const float* __restrict__ x, const float* __restrict__ bias,
       const float* __restrict__ v) {
    extern __shared__ uint32_t sm[];
    uint32_t* Ah = sm;                        // [32][PPAD]
    uint32_t* Al = Ah + 32 * PPAD;
    uint32_t* Bh = Al + 32 * PPAD;            // [128][PPAD]
    uint32_t* Bl = Bh + 128 * PPAD;
    float* XI   = (float*)(Bl + 128 * PPAD);  // [2][128]
    float* BSs  = XI + 256;
    float* VS   = BSs + 128;
    float* PART = VS + 128;                   // [8][32]

    const int p = blockIdx.x, b = blockIdx.y;
    const int i1 = p, i2 = NN - 1 - p;
    const int tid = threadIdx.x;
    const int wid = tid >> 5, lid = tid & 31;
    const int g = lid >> 2, tig = lid & 3;
    const float* xb = x + (size_t)b * NN * DD;

    if (tid < 128) {
        XI[tid]       = xb[(size_t)i1 * DD + tid];
        XI[128 + tid] = xb[(size_t)i2 * DD + tid];
        BSs[tid] = bias[tid];
        VS[tid]  = v[tid];
    }
    #pragma unroll
    for (int k = 0; k < 8; k++) {
        int e = tid + k * 256;
        int r = e >> 4, c4 = e & 15;
        ((uint4*)(Bh + r * PPAD))[c4] = ((const uint4*)d_wbh)[e];
        ((uint4*)(Bl + r * PPAD))[c4] = ((const uint4*)d_wbl)[e];
    }
    __syncthreads();

    for (int xi = 0; xi < 2; xi++) {
        const int ii = xi ? i2 : i1;
        const float* xisel = XI + xi * 128;
        for (int j0 = 0; j0 < NN; j0 += 32) {
            if (j0 + 31 < ii) continue;
            const int jmin = (ii > j0) ? (ii - j0) : 0;

            // A build: 32 rows; thread = (r = tid>>3, 16-d group)
            {
                int r  = tid >> 3;
                int dg = (tid & 7) * 16;
                const float4* xr  = (const float4*)(xb + (size_t)(j0 + r) * DD + dg);
                const float4* xi4 = (const float4*)(xisel + dg);
                uint32_t* ahr = Ah + r * PPAD + (dg >> 1);
                uint32_t* alr = Al + r * PPAD + (dg >> 1);
                #pragma unroll
                for (int q = 0; q < 4; q++) {
                    float4 xv = xr[q], iv = xi4[q];
                    uint32_t h0, l0, h1, l1;
                    split2(xv.x * iv.x, xv.y * iv.y, h0, l0);
                    split2(xv.z * iv.z, xv.w * iv.w, h1, l1);
                    ahr[q * 2]     = h0;
                    ahr[q * 2 + 1] = h1;
                    alr[q * 2]     = l0;
                    alr[q * 2 + 1] = l1;
                }
            }
            __syncthreads();

            float acc[2][2][4];
            #pragma unroll
            for (int m = 0; m < 2; m++)
                #pragma unroll
                for (int n = 0; n < 2; n++)
                    #pragma unroll
                    for (int q = 0; q < 4; q++) acc[m][n][q] = 0.f;

            #pragma unroll
            for (int k = 0; k < 8; k++) {
                uint32_t ah[2][4], al[2][4];
                #pragma unroll
                for (int m = 0; m < 2; m++) {
                    const uint32_t* aph = Ah + (m * 16 + g) * PPAD + k * 8 + tig;
                    const uint32_t* apl = Al + (m * 16 + g) * PPAD + k * 8 + tig;
                    ah[m][0] = aph[0];            ah[m][1] = aph[8 * PPAD];
                    ah[m][2] = aph[4];            ah[m][3] = aph[8 * PPAD + 4];
                    al[m][0] = apl[0];            al[m][1] = apl[8 * PPAD];
                    al[m][2] = apl[4];            al[m][3] = apl[8 * PPAD + 4];
                }
                #pragma unroll
                for (int nf = 0; nf < 2; nf++) {
                    const uint32_t* bph = Bh + (wid * 16 + nf * 8 + g) * PPAD + k * 8 + tig;
                    const uint32_t* bpl = Bl + (wid * 16 + nf * 8 + g) * PPAD + k * 8 + tig;
                    uint32_t bh0 = bph[0], bh1 = bph[4];
                    uint32_t bl0 = bpl[0], bl1 = bpl[4];
                    mma_bf16(acc[0][nf], ah[0], bh0, bh1);
                    mma_bf16(acc[1][nf], ah[1], bh0, bh1);
                    mma_bf16(acc[0][nf], ah[0], bl0, bl1);
                    mma_bf16(acc[1][nf], ah[1], bl0, bl1);
                    mma_bf16(acc[0][nf], al[0], bh0, bh1);
                    mma_bf16(acc[1][nf], al[1], bh0, bh1);
                }
            }

            // epilogue: tanh + v-dot over this warp's 16 cols
            float prt[4] = {0.f, 0.f, 0.f, 0.f};
            #pragma unroll
            for (int m = 0; m < 2; m++) {
                #pragma unroll
                for (int nf = 0; nf < 2; nf++) {
                    int c0 = wid * 16 + nf * 8 + 2 * tig;
                    float v0 = VS[c0], v1 = VS[c0 + 1];
                    float b0 = BSs[c0], b1 = BSs[c0 + 1];
                    prt[2 * m + 0] += v0 * tanh_approx(acc[m][nf][0] + b0)
                                    + v1 * tanh_approx(acc[m][nf][1] + b1);
                    prt[2 * m + 1] += v0 * tanh_approx(acc[m][nf][2] + b0)
                                    + v1 * tanh_approx(acc[m][nf][3] + b1);
                }
            }
            #pragma unroll
            for (int o = 1; o <= 2; o <<= 1) {
                prt[0] += __shfl_xor_sync(0xffffffffu, prt[0], o);
                prt[1] += __shfl_xor_sync(0xffffffffu, prt[1], o);
                prt[2] += __shfl_xor_sync(0xffffffffu, prt[2], o);
                prt[3] += __shfl_xor_sync(0xffffffffu, prt[3], o);
            }
            if (tig == 0) {
                PART[wid * 32 + g]      = prt[0];
                PART[wid * 32 + g + 8]  = prt[1];
                PART[wid * 32 + g + 16] = prt[2];
                PART[wid * 32 + g + 24] = prt[3];
            }
            __syncthreads();
            if (tid < 32 && tid >= jmin) {
                float lg = 0.f;
                #pragma unroll
                for (int w = 0; w < 8; w++) lg += PART[w * 32 + tid];
                int j = j0 + tid;
                d_logits[((size_t)b * NN + ii) * NN + j] = lg;
                d_logits[((size_t)b * NN + j) * NN + ii] = lg;
            }
            __syncthreads();
        }
    }
}

// ============================================================================
// Kernel 2r: per-row max and 1/sum(exp).
// ============================================================================
__global__ void __launch_bounds__(256)
k2r_rowstat() {
    const int b = blockIdx.y;
    const int row = blockIdx.x * 8 + (threadIdx.x >> 5);
    const int lane = threadIdx.x & 31;
    const float* rp = d_logits + ((size_t)b * NN + row) * NN;

    float4 a0 = ((const float4*)rp)[lane * 2];
    float4 a1 = ((const float4*)rp)[lane * 2 + 1];
    float m = fmaxf(fmaxf(fmaxf(a0.x, a0.y), fmaxf(a0.z, a0.w)),
                    fmaxf(fmaxf(a1.x, a1.y), fmaxf(a1.z, a1.w)));
    #pragma unroll
    for (int o = 16; o > 0; o >>= 1) m = fmaxf(m, __shfl_xor_sync(0xffffffffu, m, o));

    float s = exp2f((a0.x - m) * LOG2E) + exp2f((a0.y - m) * LOG2E)
            + exp2f((a0.z - m) * LOG2E) + exp2f((a0.w - m) * LOG2E)
            + exp2f((a1.x - m) * LOG2E) + exp2f((a1.y - m) * LOG2E)
            + exp2f((a1.z - m) * LOG2E) + exp2f((a1.w - m) * LOG2E);
    #pragma unroll
    for (int o = 16; o > 0; o >>= 1) s += __shfl_xor_sync(0xffffffffu, s, o);

    if (lane == 0) {
        d_rowM[b * NN + row]  = m;
        d_rowIS[b * NN + row] = 1.f / s;
    }
}

// ============================================================================
// Kernel 3 (tensor-core, verified R8/R13): per CTA 32 i-rows.
// stage1: agg = att @ x; stage2: h = [agg | x] @ [pwa^T ; pwoa^T]; BN/selu/pool.
// ============================================================================
#define SMEM3 ((2 * 32 * PPAD + 2 * 128 * PPAD) * 4 + (32 * 132 + 256) * 4)

__global__ void __launch_bounds__(256, 2)
k3_tc(const float* __restrict__ pool_w, const float* __restrict__ pool_b) {
    extern __shared__ uint32_t sm3u[];
    uint32_t* Ah = sm3u;                       // [32][PPAD]
    uint32_t* Al = Ah + 32 * PPAD;
    uint32_t* Bh = Al + 32 * PPAD;             // [128][PPAD]
    uint32_t* Bl = Bh + 128 * PPAD;
    float* Ag   = (float*)(Bl + 128 * PPAD);   // [32][132]; doubles as Et
    float* PART = Ag + 32 * 132;               // [256]

    const int b = blockIdx.y;
    const int it0 = blockIdx.x * 32;
    const int tid = threadIdx.x;
    const int wid = tid >> 5, lid = tid & 31;
    const int g = lid >> 2, tig = lid & 3;

    float acc[2][2][4];
    #pragma unroll
    for (int m = 0; m < 2; m++)
        #pragma unroll
        for (int n = 0; n < 2; n++)
            #pragma unroll
            for (int q = 0; q < 4; q++) acc[m][n][q] = 0.f;

    // ---------------- stage 1: agg = att @ x ----------------
    for (int ch = 0; ch < 2; ch++) {
        const int j0 = ch * 128;
        #pragma unroll
        for (int k = 0; k < 4; k++) {
            int e = tid + k * 256;
            int jr = e >> 3, ic4 = e & 7;
            int row = j0 + jr;
            float M  = d_rowM[b * NN + row];
            float IS = d_rowIS[b * NN + row];
            float4 rv = ((const float4*)(d_logits + ((size_t)b * NN + row) * NN + it0))[ic4];
            Ag[(ic4 * 4 + 0) * 132 + jr] = exp2f((rv.x - M) * LOG2E) * IS;
            Ag[(ic4 * 4 + 1) * 132 + jr] = exp2f((rv.y - M) * LOG2E) * IS;
            Ag[(ic4 * 4 + 2) * 132 + jr] = exp2f((rv.z - M) * LOG2E) * IS;
            Ag[(ic4 * 4 + 3) * 132 + jr] = exp2f((rv.w - M) * LOG2E) * IS;
        }
        __syncthreads();
        #pragma unroll
        for (int k = 0; k < 8; k++) {
            int e = tid + k * 256;
            int i = e >> 6, pp = e & 63;
            float2 v2 = *(const float2*)(Ag + i * 132 + 2 * pp);
            uint32_t hi, lo;
            split2(v2.x, v2.y, hi, lo);
            Ah[i * PPAD + pp] = hi;
            Al[i * PPAD + pp] = lo;
        }
        #pragma unroll
        for (int k = 0; k < 8; k++) {
            int e = tid + k * 256;
            int r = e >> 4, c4 = e & 15;
            ((uint4*)(Bh + r * PPAD))[c4] =
                ((const uint4*)(d_xth + ((size_t)b * DD + r) * 128 + ch * 64))[c4];
            ((uint4*)(Bl + r * PPAD))[c4] =
                ((const uint4*)(d_xtl + ((size_t)b * DD + r) * 128 + ch * 64))[c4];
        }
        __syncthreads();
        #pragma unroll
        for (int k = 0; k < 8; k++) {
            uint32_t ah[2][4], al[2][4];
            #pragma unroll
            for (int m = 0; m < 2; m++) {
                const uint32_t* aph = Ah + (m * 16 + g) * PPAD + k * 8 + tig;
                const uint32_t* apl = Al + (m * 16 + g) * PPAD + k * 8 + tig;
                ah[m][0] = aph[0];            ah[m][1] = aph[8 * PPAD];
                ah[m][2] = aph[4];            ah[m][3] = aph[8 * PPAD + 4];
                al[m][0] = apl[0];            al[m][1] = apl[8 * PPAD];
                al[m][2] = apl[4];            al[m][3] = apl[8 * PPAD + 4];
            }
            #pragma unroll
            for (int nf = 0; nf < 2; nf++) {
                const uint32_t* bph = Bh + (wid * 16 + nf * 8 + g) * PPAD + k * 8 + tig;
                const uint32_t* bpl = Bl + (wid * 16 + nf * 8 + g) * PPAD + k * 8 + tig;
                uint32_t bh0 = bph[0], bh1 = bph[4];
                uint32_t bl0 = bpl[0], bl1 = bpl[4];
                mma_bf16(acc[0][nf], ah[0], bh0, bh1);
                mma_bf16(acc[1][nf], ah[1], bh0, bh1);
                mma_bf16(acc[0][nf], ah[0], bl0, bl1);
                mma_bf16(acc[1][nf], ah[1], bl0, bl1);
                mma_bf16(acc[0][nf], al[0], bh0, bh1);
                mma_bf16(acc[1][nf], al[1], bh0, bh1);
            }
        }
        __syncthreads();
    }
    #pragma unroll
    for (int m = 0; m < 2; m++)
        #pragma unroll
        for (int nf = 0; nf < 2; nf++) {
            int c0 = wid * 16 + nf * 8 + 2 * tig;
            int r = m * 16 + g;
            Ag[r * 132 + c0]       = acc[m][nf][0];
            Ag[r * 132 + c0 + 1]   = acc[m][nf][1];
            Ag[(r + 8) * 132 + c0]     = acc[m][nf][2];
            Ag[(r + 8) * 132 + c0 + 1] = acc[m][nf][3];
        }
    __syncthreads();

    // ---------------- stage 2: h = [agg | x] @ [pwaT ; pwoaT] ----------------
    float hacc[2][2][4];
    #pragma unroll
    for (int m = 0; m < 2; m++)
        #pragma unroll
        for (int n = 0; n < 2; n++)
            #pragma unroll
            for (int q = 0; q < 4; q++) hacc[m][n][q] = 0.f;

    for (int ch = 0; ch < 2; ch++) {
        if (ch == 0) {
            #pragma unroll
            for (int k = 0; k < 8; k++) {
                int e = tid + k * 256;
                int i = e >> 6, pp = e & 63;
                float2 v2 = *(const float2*)(Ag + i * 132 + 2 * pp);
                uint32_t hi, lo;
                split2(v2.x, v2.y, hi, lo);
                Ah[i * PPAD + pp] = hi;
                Al[i * PPAD + pp] = lo;
            }
        } else {
            #pragma unroll
            for (int k = 0; k < 2; k++) {
                int e = tid + k * 256;
                int r = e >> 4, c4 = e & 15;
                ((uint4*)(Ah + r * PPAD))[c4] =
                    ((const uint4*)(d_xrh + ((size_t)b * NN + it0 + r) * 64))[c4];
                ((uint4*)(Al + r * PPAD))[c4] =
                    ((const uint4*)(d_xrl + ((size_t)b * NN + it0 + r) * 64))[c4];
            }
        }
        const uint32_t* srcH = ch ? d_poh : d_pah;
        const uint32_t* srcL = ch ? d_pol : d_pal;
        #pragma unroll
        for (int k = 0; k < 8; k++) {
            int e = tid + k * 256;
            int r = e >> 4, c4 = e & 15;
            ((uint4*)(Bh + r * PPAD))[c4] = ((const uint4*)(srcH + r * 64))[c4];
            ((uint4*)(Bl + r * PPAD))[c4] = ((const uint4*)(srcL + r * 64))[c4];
        }
        __syncthreads();
        #pragma unroll
        for (int k = 0; k < 8; k++) {
            uint32_t ah[2][4], al[2][4];
            #pragma unroll
            for (int m = 0; m < 2; m++) {
                const uint32_t* aph = Ah + (m * 16 + g) * PPAD + k * 8 + tig;
                const uint32_t* apl = Al + (m * 16 + g) * PPAD + k * 8 + tig;
                ah[m][0] = aph[0];            ah[m][1] = aph[8 * PPAD];
                ah[m][2] = aph[4];            ah[m][3] = aph[8 * PPAD + 4];
                al[m][0] = apl[0];            al[m][1] = apl[8 * PPAD];
                al[m][2] = apl[4];            al[m][3] = apl[8 * PPAD + 4];
            }
            #pragma unroll
            for (int nf = 0; nf < 2; nf++) {
                const uint32_t* bph = Bh + (wid * 16 + nf * 8 + g) * PPAD + k * 8 + tig;
                const uint32_t* bpl = Bl + (wid * 16 + nf * 8 + g) * PPAD + k * 8 + tig;
                uint32_t bh0 = bph[0], bh1 = bph[4];
                uint32_t bl0 = bpl[0], bl1 = bpl[4];
                mma_bf16(hacc[0][nf], ah[0], bh0, bh1);
                mma_bf16(hacc[1][nf], ah[1], bh0, bh1);
                mma_bf16(hacc[0][nf], ah[0], bl0, bl1);
                mma_bf16(hacc[1][nf], ah[1], bl0, bl1);
                mma_bf16(hacc[0][nf], al[0], bh0, bh1);
                mma_bf16(hacc[1][nf], al[1], bh0, bh1);
            }
        }
        __syncthreads();
    }

    // ---------------- epilogue: BN + selu + store + pool ----------------
    const float SELU_S = 1.0507009873554805f;
    const float SELU_A = 1.6732632423543772f;
    float prt[4] = {0.f, 0.f, 0.f, 0.f};
    #pragma unroll
    for (int m = 0; m < 2; m++) {
        #pragma unroll
        for (int nf = 0; nf < 2; nf++) {
            int c0 = wid * 16 + nf * 8 + 2 * tig;
            float sc0 = d_bnsc[c0], of0 = d_bnof[c0];
            float sc1 = d_bnsc[c0 + 1], of1 = d_bnof[c0 + 1];
            float pw0 = pool_w[c0], pw1 = pool_w[c0 + 1];
            #pragma unroll
            for (int half = 0; half < 2; half++) {
                int r = m * 16 + g + half * 8;
                float hv0 = hacc[m][nf][half * 2]     * sc0 + of0;
                float hv1 = hacc[m][nf][half * 2 + 1] * sc1 + of1;
                hv0 = (hv0 > 0.f) ? SELU_S * hv0 : SELU_S * SELU_A * (expf(hv0) - 1.f);
                hv1 = (hv1 > 0.f) ? SELU_S * hv1 : SELU_S * SELU_A * (expf(hv1) - 1.f);
                *(float2*)(d_h + ((size_t)b * NN + it0 + r) * DD + c0) =
                    make_float2(hv0, hv1);
                prt[m * 2 + half] += hv0 * pw0 + hv1 * pw1;
            }
        }
    }
    #pragma unroll
    for (int o = 1; o <= 2; o <<= 1) {
        prt[0] += __shfl_xor_sync(0xffffffffu, prt[0], o);
        prt[1] += __shfl_xor_sync(0xffffffffu, prt[1], o);
        prt[2] += __shfl_xor_sync(0xffffffffu, prt[2], o);
        prt[3] += __shfl_xor_sync(0xffffffffu, prt[3], o);
    }
    if (tig == 0) {
        PART[wid * 32 + g]      = prt[0];
        PART[wid * 32 + g + 8]  = prt[1];
        PART[wid * 32 + g + 16] = prt[2];
        PART[wid * 32 + g + 24] = prt[3];
    }
    __syncthreads();
    if (tid < 32) {
        float pacc = 0.f;
        #pragma unroll
        for (int w = 0; w < 8; w++) pacc += PART[w * 32 + tid];
        float sg = 1.f / (1.f + expf(-(pacc + pool_b[0])));
        d_scores[b * NN + it0 + tid] = sg;
    }
}

// ============================================================================
// Kernel 4: fused rank-select + gather.
// ============================================================================
__global__ void __launch_bounds__(256)
k4_topk(float* __restrict__ out) {
    const int b = blockIdx.y;
    const int q = blockIdx.x;
    const int tid = threadIdx.x;
    __shared__ float ss[NN];
    __shared__ int sp[KP];

    float s = d_scores[b * NN + tid];
    ss[tid] = s;
    __syncthreads();

    int r = 0;
    #pragma unroll 16
    for (int j = 0; j < NN; j++) {
        float sj = ss[j];
        r += (sj > s) || (sj == s && j < tid);
    }
    if (r < KP) sp[r] = tid;
    __syncthreads();

    #pragma unroll
    for (int k = 0; k < 4; k++) {
        int e = q * 1024 + k * 256 + tid;
        int row = e >> 5, c4 = e & 31;
        int j = sp[row];
        float sv = ss[j];
        float4 v = ((const float4*)(d_h + ((size_t)b * NN + j) * DD))[c4];
        ((float4*)(out + ((size_t)b * KP + row) * DD))[c4] =
            make_float4(v.x * sv, v.y * sv, v.z * sv, v.w * sv);
    }
}

// ============================================================================
extern "C" void kernel_launch(void* const* d_in, const int* in_sizes, int n_in,
                              void* d_out, int out_size) {
    const float* x        = (const float*)d_in[0];
    const float* apw      = (const float*)d_in[1];
    const float* apb      = (const float*)d_in[2];
    const float* aweight  = (const float*)d_in[3];
    const float* pwa_w    = (const float*)d_in[4];
    const float* pwa_b    = (const float*)d_in[5];
    const float* pwoa_w   = (const float*)d_in[6];
    const float* pwoa_b   = (const float*)d_in[7];
    const float* bn_g     = (const float*)d_in[8];
    const float* bn_b     = (const float*)d_in[9];
    const float* bn_m     = (const float*)d_in[10];
    const float* bn_v     = (const float*)d_in[11];
    const float* pool_w   = (const float*)d_in[12];
    const float* pool_b   = (const float*)d_in[13];
    float* out = (float*)d_out;

    cudaFuncSetAttribute(k1_mma, cudaFuncAttributeMaxDynamicSharedMemorySize, SMEM1_REQ);
    cudaFuncSetAttribute(k3_tc,  cudaFuncAttributeMaxDynamicSharedMemorySize, SMEM3);

    k0_prep<<<1185, 256>>>(apw, x, pwa_w, pwoa_w, pwa_b, pwoa_b,
                           bn_g, bn_b, bn_m, bn_v);
    k1_mma<<<dim3(NN / 2, BB), 256, SMEM1_REQ>>>(x, apb, aweight);
    k2r_rowstat<<<dim3(NN / 8, BB), 256>>>();
    k3_tc<<<dim3(NN / 32, BB), 256, SMEM3>>>(pool_w, pool_b);
    k4_topk<<<dim3(4, BB), 256>>>(out);
}